// round 3
// baseline (speedup 1.0000x reference)
#include <cuda_runtime.h>
#include <cuda_bf16.h>
#include <mma.h>
#include <cstdint>

using namespace nvcuda;
typedef __nv_bfloat16 bf16;

#define NHEADS 16
#define HD     128
#define CDIM   2048
#define NV     6144     // visual tokens (8*24*32)
#define LT     128      // text tokens
#define NTOK   6272     // NV + LT
#define NG     4        // groups (gt=1, gh=2, gw=2)
#define LVG    1536     // visual tokens per group
#define LSEQ   1664     // LVG + LT
#define EPSV   1e-6f

// ---------------------------------------------------------------------------
// Scratch (static device arrays; no allocations allowed)
// ---------------------------------------------------------------------------
__device__ float g_QG[(size_t)NG * NHEADS * LSEQ * HD];   // [g][h][l][d]
__device__ float g_KG[(size_t)NG * NHEADS * LSEQ * HD];
__device__ float g_VG[(size_t)NG * NHEADS * LSEQ * HD];
__device__ float g_OG[(size_t)NG * LSEQ * CDIM];          // [g][l][h*HD+d]
__device__ float g_X [(size_t)NTOK * CDIM];               // attention output, token order

__device__ __forceinline__ void split2(float x, bf16& h, bf16& l) {
    h = __float2bfloat16(x);
    l = __float2bfloat16(x - __bfloat162float(h));
}

typedef wmma::fragment<wmma::matrix_a, 16, 16, 16, bf16, wmma::row_major>  FragA;
typedef wmma::fragment<wmma::matrix_b, 16, 16, 16, bf16, wmma::col_major>  FragBc;
typedef wmma::fragment<wmma::matrix_b, 16, 16, 16, bf16, wmma::row_major>  FragBr;
typedef wmma::fragment<wmma::accumulator, 16, 16, 16, float>               FragC;

// ---------------------------------------------------------------------------
// QKV projection GEMM (BM=64, BN=128 = one head, BK=32) + fused epilogue:
// bias, RMSNorm (q/k), rotary (visual q/k), group scatter.  bf16x3 split.
// grid = (98, 16, 3)  z: 0=Q 1=K 2=V
// ---------------------------------------------------------------------------
__global__ __launch_bounds__(256) void qkv_gemm_kernel(
    const float* __restrict__ vis, const float* __restrict__ txt,
    const float* __restrict__ rope,
    const float* __restrict__ Wq, const float* __restrict__ bq,
    const float* __restrict__ Wk, const float* __restrict__ bk,
    const float* __restrict__ Wv, const float* __restrict__ bv,
    const float* __restrict__ qn, const float* __restrict__ kn)
{
    __shared__ float smem[8192];            // 32 KB (also holds result tile)
    bf16* sAh = (bf16*)smem;                // 64 x 40
    bf16* sAl = sAh + 64 * 40;
    bf16* sBh = sAl + 64 * 40;              // 128 x 40
    bf16* sBl = sBh + 128 * 40;

    const int tid  = threadIdx.x;
    const int wid  = tid >> 5;
    const int wm   = wid & 3;               // warp row (4 x 16 = 64)
    const int wn   = wid >> 2;              // warp col (2 x 64 = 128)
    const int mode = blockIdx.z;
    const int head = blockIdx.y;
    const int m0   = blockIdx.x * 64;
    const float* W = (mode == 0) ? Wq : (mode == 1) ? Wk : Wv;

    FragC acc[4];
    #pragma unroll
    for (int f = 0; f < 4; f++) wmma::fill_fragment(acc[f], 0.0f);

    for (int kt = 0; kt < CDIM; kt += 32) {
        // A tile 64x32
        #pragma unroll
        for (int i = 0; i < 2; i++) {
            int idx = tid + i * 256;
            int r = idx >> 3, c4 = (idx & 7) << 2;
            int tok = m0 + r;
            const float* src = (tok < NV) ? (vis + (size_t)tok * CDIM)
                                          : (txt + (size_t)(tok - NV) * CDIM);
            float4 v = *(const float4*)(src + kt + c4);
            int o = r * 40 + c4;
            split2(v.x, sAh[o+0], sAl[o+0]); split2(v.y, sAh[o+1], sAl[o+1]);
            split2(v.z, sAh[o+2], sAl[o+2]); split2(v.w, sAh[o+3], sAl[o+3]);
        }
        // B tile 128x32 (rows of W for this head)
        #pragma unroll
        for (int i = 0; i < 4; i++) {
            int idx = tid + i * 256;
            int r = idx >> 3, c4 = (idx & 7) << 2;
            float4 v = *(const float4*)(W + (size_t)(head * HD + r) * CDIM + kt + c4);
            int o = r * 40 + c4;
            split2(v.x, sBh[o+0], sBl[o+0]); split2(v.y, sBh[o+1], sBl[o+1]);
            split2(v.z, sBh[o+2], sBl[o+2]); split2(v.w, sBh[o+3], sBl[o+3]);
        }
        __syncthreads();
        #pragma unroll
        for (int ks = 0; ks < 2; ks++) {
            FragA ah, al;
            wmma::load_matrix_sync(ah, sAh + wm * 16 * 40 + ks * 16, 40);
            wmma::load_matrix_sync(al, sAl + wm * 16 * 40 + ks * 16, 40);
            #pragma unroll
            for (int f = 0; f < 4; f++) {
                FragBc bh, bl;
                wmma::load_matrix_sync(bh, sBh + (wn * 64 + f * 16) * 40 + ks * 16, 40);
                wmma::load_matrix_sync(bl, sBl + (wn * 64 + f * 16) * 40 + ks * 16, 40);
                wmma::mma_sync(acc[f], ah, bh, acc[f]);
                wmma::mma_sync(acc[f], ah, bl, acc[f]);
                wmma::mma_sync(acc[f], al, bh, acc[f]);
            }
        }
        __syncthreads();
    }

    // stage result tile to smem (reuse)
    float* sC = smem;                       // 64 x 128
    #pragma unroll
    for (int f = 0; f < 4; f++)
        wmma::store_matrix_sync(sC + wm * 16 * 128 + wn * 64 + f * 16, acc[f], 128,
                                wmma::mem_row_major);
    __syncthreads();

    // epilogue: 4 threads per row, 32 contiguous cols each
    const float* bias = (mode == 0) ? bq : (mode == 1) ? bk : bv;
    const int r  = tid >> 2;
    const int q4 = tid & 3;
    const int c0 = q4 * 32;
    const int tok = m0 + r;

    float vals[32];
    #pragma unroll
    for (int c = 0; c < 32; c++)
        vals[c] = sC[r * 128 + c0 + c] + bias[head * HD + c0 + c];

    if (mode < 2) {
        const float* w = (mode == 0) ? qn : kn;
        float ss = 0.f;
        #pragma unroll
        for (int c = 0; c < 32; c++) ss += vals[c] * vals[c];
        ss += __shfl_xor_sync(0xffffffffu, ss, 1);
        ss += __shfl_xor_sync(0xffffffffu, ss, 2);
        float rstd = rsqrtf(ss * (1.0f / HD) + EPSV);
        #pragma unroll
        for (int c = 0; c < 32; c++) vals[c] = vals[c] * rstd * w[c0 + c];

        if (tok < NV) {  // rotary on visual only
            const float* rp = rope + (size_t)tok * 256 + c0 * 2;
            #pragma unroll
            for (int i = 0; i < 16; i++) {
                float x0 = vals[2 * i], x1 = vals[2 * i + 1];
                vals[2 * i]     = rp[i * 4 + 0] * x0 + rp[i * 4 + 1] * x1;
                vals[2 * i + 1] = rp[i * 4 + 2] * x0 + rp[i * 4 + 3] * x1;
            }
        }
    }

    float* dst = (mode == 0) ? g_QG : (mode == 1) ? g_KG : g_VG;
    if (tok < NV) {
        int t = tok / 768, rem = tok - t * 768;
        int hh = rem >> 5, ww = rem & 31;
        int g   = (hh / 12) * 2 + (ww >> 4);
        int pos = t * 192 + (hh % 12) * 16 + (ww & 15);
        float* d = dst + ((size_t)((g * NHEADS + head) * LSEQ + pos)) * HD + c0;
        #pragma unroll
        for (int c = 0; c < 32; c++) d[c] = vals[c];
    } else {
        int pos = LVG + (tok - NV);         // text token appears in all groups
        #pragma unroll
        for (int g = 0; g < NG; g++) {
            float* d = dst + ((size_t)((g * NHEADS + head) * LSEQ + pos)) * HD + c0;
            #pragma unroll
            for (int c = 0; c < 32; c++) d[c] = vals[c];
        }
    }
}

// ---------------------------------------------------------------------------
// Attention: two-pass softmax (pass1 rowmax, pass2 exp/sum + PV accumulate).
// BM=64, BN=64, bf16x3 split. grid = (26, 16, 4), 256 threads.
// ---------------------------------------------------------------------------
#define QTILE (64 * 136)
#define PTILE (64 * 72)
#define ATT_SMEM_BYTES ((6 * QTILE + 2 * PTILE) * 2 + 64 * 68 * 4)  // 140,288 B

__global__ __launch_bounds__(256) void attn_kernel(float scale)
{
    extern __shared__ char smem[];
    bf16* sQh = (bf16*)smem;            // 64 x 136
    bf16* sQl = sQh + QTILE;
    bf16* sKh = sQl + QTILE;
    bf16* sKl = sKh + QTILE;
    bf16* sVh = sKl + QTILE;
    bf16* sVl = sVh + QTILE;
    bf16* sPh = sVl + QTILE;            // 64 x 72
    bf16* sPl = sPh + PTILE;
    float* sS = (float*)(sPl + PTILE);  // 64 x 68 fp32

    const int tid = threadIdx.x;
    const int wid = tid >> 5;
    const int wm  = wid & 3;          // 4 warps over 64 rows
    const int wn  = wid >> 2;         // 2 warps over cols
    const int q0  = blockIdx.x * 64;
    const int h   = blockIdx.y;
    const int g   = blockIdx.z;
    const size_t base = (size_t)(g * NHEADS + h) * LSEQ * HD;
    const float* Qp = g_QG + base;
    const float* Kp = g_KG + base;
    const float* Vp = g_VG + base;

    // load Q tile (scaled, split)
    #pragma unroll
    for (int i = 0; i < 8; i++) {
        int idx = tid + i * 256;
        int r = idx >> 5, c4 = (idx & 31) << 2;
        float4 v = *(const float4*)(Qp + (size_t)(q0 + r) * HD + c4);
        int o = r * 136 + c4;
        split2(v.x * scale, sQh[o+0], sQl[o+0]);
        split2(v.y * scale, sQh[o+1], sQl[o+1]);
        split2(v.z * scale, sQh[o+2], sQl[o+2]);
        split2(v.w * scale, sQh[o+3], sQl[o+3]);
    }
    __syncthreads();

    const int rr = tid >> 2;          // softmax row of this thread
    const int qq = tid & 3;           // col quarter
    float rmax = -1e30f;

    // ---- pass 1: row max ----
    for (int kt = 0; kt < LSEQ; kt += 64) {
        #pragma unroll
        for (int i = 0; i < 8; i++) {
            int idx = tid + i * 256;
            int r = idx >> 5, c4 = (idx & 31) << 2;
            float4 v = *(const float4*)(Kp + (size_t)(kt + r) * HD + c4);
            int o = r * 136 + c4;
            split2(v.x, sKh[o+0], sKl[o+0]); split2(v.y, sKh[o+1], sKl[o+1]);
            split2(v.z, sKh[o+2], sKl[o+2]); split2(v.w, sKh[o+3], sKl[o+3]);
        }
        __syncthreads();
        FragC sacc[2];
        wmma::fill_fragment(sacc[0], 0.f);
        wmma::fill_fragment(sacc[1], 0.f);
        #pragma unroll
        for (int ks = 0; ks < 8; ks++) {
            FragA ah, al;
            wmma::load_matrix_sync(ah, sQh + wm * 16 * 136 + ks * 16, 136);
            wmma::load_matrix_sync(al, sQl + wm * 16 * 136 + ks * 16, 136);
            #pragma unroll
            for (int f = 0; f < 2; f++) {
                FragBc bh, bl;
                wmma::load_matrix_sync(bh, sKh + (wn * 32 + f * 16) * 136 + ks * 16, 136);
                wmma::load_matrix_sync(bl, sKl + (wn * 32 + f * 16) * 136 + ks * 16, 136);
                wmma::mma_sync(sacc[f], ah, bh, sacc[f]);
                wmma::mma_sync(sacc[f], ah, bl, sacc[f]);
                wmma::mma_sync(sacc[f], al, bh, sacc[f]);
            }
        }
        #pragma unroll
        for (int f = 0; f < 2; f++)
            wmma::store_matrix_sync(sS + wm * 16 * 68 + wn * 32 + f * 16, sacc[f], 68,
                                    wmma::mem_row_major);
        __syncthreads();
        #pragma unroll
        for (int c = 0; c < 16; c++)
            rmax = fmaxf(rmax, sS[rr * 68 + qq * 16 + c]);
        __syncthreads();
    }
    rmax = fmaxf(rmax, __shfl_xor_sync(0xffffffffu, rmax, 1));
    rmax = fmaxf(rmax, __shfl_xor_sync(0xffffffffu, rmax, 2));

    // ---- pass 2: P = exp(S - rmax), rowsum, O += P V ----
    FragC oacc[4];
    #pragma unroll
    for (int f = 0; f < 4; f++) wmma::fill_fragment(oacc[f], 0.f);
    float rsum = 0.f;

    for (int kt = 0; kt < LSEQ; kt += 64) {
        #pragma unroll
        for (int i = 0; i < 8; i++) {
            int idx = tid + i * 256;
            int r = idx >> 5, c4 = (idx & 31) << 2;
            float4 vk = *(const float4*)(Kp + (size_t)(kt + r) * HD + c4);
            int o = r * 136 + c4;
            split2(vk.x, sKh[o+0], sKl[o+0]); split2(vk.y, sKh[o+1], sKl[o+1]);
            split2(vk.z, sKh[o+2], sKl[o+2]); split2(vk.w, sKh[o+3], sKl[o+3]);
            float4 vv = *(const float4*)(Vp + (size_t)(kt + r) * HD + c4);
            split2(vv.x, sVh[o+0], sVl[o+0]); split2(vv.y, sVh[o+1], sVl[o+1]);
            split2(vv.z, sVh[o+2], sVl[o+2]); split2(vv.w, sVh[o+3], sVl[o+3]);
        }
        __syncthreads();
        FragC sacc[2];
        wmma::fill_fragment(sacc[0], 0.f);
        wmma::fill_fragment(sacc[1], 0.f);
        #pragma unroll
        for (int ks = 0; ks < 8; ks++) {
            FragA ah, al;
            wmma::load_matrix_sync(ah, sQh + wm * 16 * 136 + ks * 16, 136);
            wmma::load_matrix_sync(al, sQl + wm * 16 * 136 + ks * 16, 136);
            #pragma unroll
            for (int f = 0; f < 2; f++) {
                FragBc bh, bl;
                wmma::load_matrix_sync(bh, sKh + (wn * 32 + f * 16) * 136 + ks * 16, 136);
                wmma::load_matrix_sync(bl, sKl + (wn * 32 + f * 16) * 136 + ks * 16, 136);
                wmma::mma_sync(sacc[f], ah, bh, sacc[f]);
                wmma::mma_sync(sacc[f], ah, bl, sacc[f]);
                wmma::mma_sync(sacc[f], al, bh, sacc[f]);
            }
        }
        #pragma unroll
        for (int f = 0; f < 2; f++)
            wmma::store_matrix_sync(sS + wm * 16 * 68 + wn * 32 + f * 16, sacc[f], 68,
                                    wmma::mem_row_major);
        __syncthreads();
        #pragma unroll
        for (int c = 0; c < 16; c++) {
            float p = __expf(sS[rr * 68 + qq * 16 + c] - rmax);
            rsum += p;
            int o = rr * 72 + qq * 16 + c;
            split2(p, sPh[o], sPl[o]);
        }
        __syncthreads();
        #pragma unroll
        for (int ks = 0; ks < 4; ks++) {
            FragA ph, pl;
            wmma::load_matrix_sync(ph, sPh + wm * 16 * 72 + ks * 16, 72);
            wmma::load_matrix_sync(pl, sPl + wm * 16 * 72 + ks * 16, 72);
            #pragma unroll
            for (int f = 0; f < 4; f++) {
                FragBr vh, vl;
                wmma::load_matrix_sync(vh, sVh + ks * 16 * 136 + wn * 64 + f * 16, 136);
                wmma::load_matrix_sync(vl, sVl + ks * 16 * 136 + wn * 64 + f * 16, 136);
                wmma::mma_sync(oacc[f], ph, vh, oacc[f]);
                wmma::mma_sync(oacc[f], ph, vl, oacc[f]);
                wmma::mma_sync(oacc[f], pl, vh, oacc[f]);
            }
        }
        __syncthreads();
    }
    rsum += __shfl_xor_sync(0xffffffffu, rsum, 1);
    rsum += __shfl_xor_sync(0xffffffffu, rsum, 2);

    // stage O (reuse K/V region: 64*128 fp32 = 32 KB <= 4 bf16 tiles) and write
    float* sO = (float*)sKh;
    #pragma unroll
    for (int f = 0; f < 4; f++)
        wmma::store_matrix_sync(sO + wm * 16 * 128 + wn * 64 + f * 16, oacc[f], 128,
                                wmma::mem_row_major);
    __syncthreads();
    float inv = 1.f / rsum;
    float* outp = g_OG + ((size_t)(g * LSEQ + q0 + rr)) * CDIM + h * HD + qq * 32;
    #pragma unroll
    for (int c = 0; c < 32; c++)
        outp[c] = sO[rr * 128 + qq * 32 + c] * inv;
}

// ---------------------------------------------------------------------------
// Ungroup: visual rows scattered back to token order; text rows = mean over 4 groups
// ---------------------------------------------------------------------------
__global__ __launch_bounds__(256) void ungroup_kernel()
{
    int i = blockIdx.x * 256 + threadIdx.x;          // float4 index
    if (i >= NTOK * CDIM / 4) return;
    int tok = i >> 9;                                 // / 512 float4 per row
    int c4  = (i & 511) << 2;
    float4 res;
    if (tok < NV) {
        int t = tok / 768, rem = tok - t * 768;
        int hh = rem >> 5, ww = rem & 31;
        int g   = (hh / 12) * 2 + (ww >> 4);
        int pos = t * 192 + (hh % 12) * 16 + (ww & 15);
        res = *(const float4*)(g_OG + ((size_t)(g * LSEQ + pos)) * CDIM + c4);
    } else {
        int pos = LVG + tok - NV;
        float4 a = *(const float4*)(g_OG + ((size_t)(0 * LSEQ + pos)) * CDIM + c4);
        float4 b = *(const float4*)(g_OG + ((size_t)(1 * LSEQ + pos)) * CDIM + c4);
        float4 c = *(const float4*)(g_OG + ((size_t)(2 * LSEQ + pos)) * CDIM + c4);
        float4 d = *(const float4*)(g_OG + ((size_t)(3 * LSEQ + pos)) * CDIM + c4);
        res.x = (a.x + b.x + c.x + d.x) * 0.25f;
        res.y = (a.y + b.y + c.y + d.y) * 0.25f;
        res.z = (a.z + b.z + c.z + d.z) * 0.25f;
        res.w = (a.w + b.w + c.w + d.w) * 0.25f;
    }
    *(float4*)(g_X + (size_t)tok * CDIM + c4) = res;
}

// ---------------------------------------------------------------------------
// Output GEMM: out = X @ Wo^T + bo   (writes d_out directly, token order)
// ---------------------------------------------------------------------------
__global__ __launch_bounds__(256) void out_gemm_kernel(
    const float* __restrict__ Wo, const float* __restrict__ bo,
    float* __restrict__ out)
{
    __shared__ float smem[8192];
    bf16* sAh = (bf16*)smem;
    bf16* sAl = sAh + 64 * 40;
    bf16* sBh = sAl + 64 * 40;
    bf16* sBl = sBh + 128 * 40;

    const int tid  = threadIdx.x;
    const int wid  = tid >> 5;
    const int wm   = wid & 3;
    const int wn   = wid >> 2;
    const int head = blockIdx.y;
    const int m0   = blockIdx.x * 64;

    FragC acc[4];
    #pragma unroll
    for (int f = 0; f < 4; f++) wmma::fill_fragment(acc[f], 0.0f);

    for (int kt = 0; kt < CDIM; kt += 32) {
        #pragma unroll
        for (int i = 0; i < 2; i++) {
            int idx = tid + i * 256;
            int r = idx >> 3, c4 = (idx & 7) << 2;
            float4 v = *(const float4*)(g_X + (size_t)(m0 + r) * CDIM + kt + c4);
            int o = r * 40 + c4;
            split2(v.x, sAh[o+0], sAl[o+0]); split2(v.y, sAh[o+1], sAl[o+1]);
            split2(v.z, sAh[o+2], sAl[o+2]); split2(v.w, sAh[o+3], sAl[o+3]);
        }
        #pragma unroll
        for (int i = 0; i < 4; i++) {
            int idx = tid + i * 256;
            int r = idx >> 3, c4 = (idx & 7) << 2;
            float4 v = *(const float4*)(Wo + (size_t)(head * HD + r) * CDIM + kt + c4);
            int o = r * 40 + c4;
            split2(v.x, sBh[o+0], sBl[o+0]); split2(v.y, sBh[o+1], sBl[o+1]);
            split2(v.z, sBh[o+2], sBl[o+2]); split2(v.w, sBh[o+3], sBl[o+3]);
        }
        __syncthreads();
        #pragma unroll
        for (int ks = 0; ks < 2; ks++) {
            FragA ah, al;
            wmma::load_matrix_sync(ah, sAh + wm * 16 * 40 + ks * 16, 40);
            wmma::load_matrix_sync(al, sAl + wm * 16 * 40 + ks * 16, 40);
            #pragma unroll
            for (int f = 0; f < 4; f++) {
                FragBc bh, bl;
                wmma::load_matrix_sync(bh, sBh + (wn * 64 + f * 16) * 40 + ks * 16, 40);
                wmma::load_matrix_sync(bl, sBl + (wn * 64 + f * 16) * 40 + ks * 16, 40);
                wmma::mma_sync(acc[f], ah, bh, acc[f]);
                wmma::mma_sync(acc[f], ah, bl, acc[f]);
                wmma::mma_sync(acc[f], al, bh, acc[f]);
            }
        }
        __syncthreads();
    }

    float* sC = smem;
    #pragma unroll
    for (int f = 0; f < 4; f++)
        wmma::store_matrix_sync(sC + wm * 16 * 128 + wn * 64 + f * 16, acc[f], 128,
                                wmma::mem_row_major);
    __syncthreads();

    const int r  = tid >> 2;
    const int q4 = tid & 3;
    const int c0 = q4 * 32;
    const int tok = m0 + r;
    float* d = out + (size_t)tok * CDIM + head * HD + c0;
    #pragma unroll
    for (int c = 0; c < 32; c++)
        d[c] = sC[r * 128 + c0 + c] + bo[head * HD + c0 + c];
}

// ---------------------------------------------------------------------------
extern "C" void kernel_launch(void* const* d_in, const int* in_sizes, int n_in,
                              void* d_out, int out_size)
{
    const float* vis  = (const float*)d_in[0];
    const float* txt  = (const float*)d_in[1];
    const float* rope = (const float*)d_in[2];
    const float* Wq   = (const float*)d_in[3];
    const float* bq   = (const float*)d_in[4];
    const float* Wk   = (const float*)d_in[5];
    const float* bk   = (const float*)d_in[6];
    const float* Wv   = (const float*)d_in[7];
    const float* bv   = (const float*)d_in[8];
    const float* qn   = (const float*)d_in[9];
    const float* kn   = (const float*)d_in[10];
    const float* Wo   = (const float*)d_in[11];
    const float* bo   = (const float*)d_in[12];
    float* out = (float*)d_out;
    (void)in_sizes; (void)n_in; (void)out_size;

    cudaFuncSetAttribute(attn_kernel, cudaFuncAttributeMaxDynamicSharedMemorySize,
                         ATT_SMEM_BYTES);

    dim3 gq(98, 16, 3);
    qkv_gemm_kernel<<<gq, 256>>>(vis, txt, rope, Wq, bq, Wk, bk, Wv, bv, qn, kn);

    dim3 ga(26, 16, 4);
    attn_kernel<<<ga, 256, ATT_SMEM_BYTES>>>(0.08838834764831845f);  // 1/sqrt(128)

    ungroup_kernel<<<(NTOK * CDIM / 4 + 255) / 256, 256>>>();

    dim3 go(98, 16, 1);
    out_gemm_kernel<<<go, 256>>>(Wo, bo, out);
}

// round 4
// speedup vs baseline: 1.3557x; 1.3557x over previous
#include <cuda_runtime.h>
#include <cuda_bf16.h>
#include <mma.h>
#include <cstdint>

using namespace nvcuda;
typedef __nv_bfloat16 bf16;

#define NHEADS 16
#define HD     128
#define CDIM   2048
#define NV     6144
#define LT     128
#define NTOK   6272
#define NG     4
#define LVG    1536
#define LSEQ   1664
#define EPSV   1e-6f
#define QSCALE 0.08838834764831845f

// ---------------------------------------------------------------------------
// Scratch
// ---------------------------------------------------------------------------
#define QKV_ELEMS ((size_t)NG * NHEADS * LSEQ * HD)
__device__ bf16 g_Qh[QKV_ELEMS], g_Ql[QKV_ELEMS];
__device__ bf16 g_Kh[QKV_ELEMS], g_Kl[QKV_ELEMS];
__device__ bf16 g_Vh[QKV_ELEMS], g_Vl[QKV_ELEMS];
__device__ float g_OG[(size_t)NG * LSEQ * CDIM];
__device__ float g_X [(size_t)NTOK * CDIM];

__device__ __forceinline__ void split2(float x, bf16& h, bf16& l) {
    h = __float2bfloat16(x);
    l = __float2bfloat16(x - __bfloat162float(h));
}
__device__ __forceinline__ uint32_t pack2(bf16 a, bf16 b) {
    __nv_bfloat162 t; t.x = a; t.y = b;
    return *reinterpret_cast<uint32_t*>(&t);
}
__device__ __forceinline__ uint32_t smem_u32(const void* p) {
    return (uint32_t)__cvta_generic_to_shared(p);
}
__device__ __forceinline__ void ldsm4(uint32_t* r, uint32_t addr) {
    asm volatile("ldmatrix.sync.aligned.m8n8.x4.shared.b16 {%0,%1,%2,%3},[%4];"
                 : "=r"(r[0]), "=r"(r[1]), "=r"(r[2]), "=r"(r[3]) : "r"(addr));
}
__device__ __forceinline__ void ldsm4t(uint32_t* r, uint32_t addr) {
    asm volatile("ldmatrix.sync.aligned.m8n8.x4.trans.shared.b16 {%0,%1,%2,%3},[%4];"
                 : "=r"(r[0]), "=r"(r[1]), "=r"(r[2]), "=r"(r[3]) : "r"(addr));
}
__device__ __forceinline__ void mma_bf16(float* c, const uint32_t* a,
                                         uint32_t b0, uint32_t b1) {
    asm volatile(
        "mma.sync.aligned.m16n8k16.row.col.f32.bf16.bf16.f32 "
        "{%0,%1,%2,%3},{%4,%5,%6,%7},{%8,%9},{%0,%1,%2,%3};"
        : "+f"(c[0]), "+f"(c[1]), "+f"(c[2]), "+f"(c[3])
        : "r"(a[0]), "r"(a[1]), "r"(a[2]), "r"(a[3]), "r"(b0), "r"(b1));
}

typedef wmma::fragment<wmma::matrix_a, 16, 16, 16, bf16, wmma::row_major>  FragA;
typedef wmma::fragment<wmma::matrix_b, 16, 16, 16, bf16, wmma::col_major>  FragBc;
typedef wmma::fragment<wmma::accumulator, 16, 16, 16, float>               FragC;

#define GEMM_SMEM 65536   // max(4*128*40*2, 128*128*4)

// ---------------------------------------------------------------------------
// QKV GEMM: BM=128, BN=128(=one head), BK=32, 8 warps (4x2), warp tile 32x64.
// Epilogue: bias, RMSNorm(q/k), rotary(visual q/k), Q scale, split -> bf16 hi/lo
// grid = (49, 16, 3)
// ---------------------------------------------------------------------------
__global__ __launch_bounds__(256) void qkv_gemm_kernel(
    const float* __restrict__ vis, const float* __restrict__ txt,
    const float* __restrict__ rope,
    const float* __restrict__ Wq, const float* __restrict__ bq,
    const float* __restrict__ Wk, const float* __restrict__ bk,
    const float* __restrict__ Wv, const float* __restrict__ bv,
    const float* __restrict__ qn, const float* __restrict__ kn)
{
    extern __shared__ char smraw[];
    bf16* sAh = (bf16*)smraw;               // 128 x 40
    bf16* sAl = sAh + 128 * 40;
    bf16* sBh = sAl + 128 * 40;
    bf16* sBl = sBh + 128 * 40;

    const int tid  = threadIdx.x;
    const int w    = tid >> 5;
    const int wm   = w >> 1;                // 0..3 : 32-row slab
    const int wn   = w & 1;                 // 0..1 : 64-col slab
    const int mode = blockIdx.z;
    const int head = blockIdx.y;
    const int m0   = blockIdx.x * 128;
    const float* W = (mode == 0) ? Wq : (mode == 1) ? Wk : Wv;

    FragC acc[2][4];
    #pragma unroll
    for (int mi = 0; mi < 2; mi++)
        #pragma unroll
        for (int f = 0; f < 4; f++) wmma::fill_fragment(acc[mi][f], 0.0f);

    for (int kt = 0; kt < CDIM; kt += 32) {
        #pragma unroll
        for (int i = 0; i < 4; i++) {
            int idx = tid + i * 256;
            int r = idx >> 3, c4 = (idx & 7) << 2;
            int tok = m0 + r;
            const float* src = (tok < NV) ? (vis + (size_t)tok * CDIM)
                                          : (txt + (size_t)(tok - NV) * CDIM);
            float4 v = *(const float4*)(src + kt + c4);
            int o = r * 40 + c4;
            split2(v.x, sAh[o+0], sAl[o+0]); split2(v.y, sAh[o+1], sAl[o+1]);
            split2(v.z, sAh[o+2], sAl[o+2]); split2(v.w, sAh[o+3], sAl[o+3]);
            float4 b = *(const float4*)(W + (size_t)(head * HD + r) * CDIM + kt + c4);
            split2(b.x, sBh[o+0], sBl[o+0]); split2(b.y, sBh[o+1], sBl[o+1]);
            split2(b.z, sBh[o+2], sBl[o+2]); split2(b.w, sBh[o+3], sBl[o+3]);
        }
        __syncthreads();
        #pragma unroll
        for (int ks = 0; ks < 2; ks++) {
            FragA ah[2], al[2];
            #pragma unroll
            for (int mi = 0; mi < 2; mi++) {
                wmma::load_matrix_sync(ah[mi], sAh + (wm * 32 + mi * 16) * 40 + ks * 16, 40);
                wmma::load_matrix_sync(al[mi], sAl + (wm * 32 + mi * 16) * 40 + ks * 16, 40);
            }
            #pragma unroll
            for (int f = 0; f < 4; f++) {
                FragBc bh, bl;
                wmma::load_matrix_sync(bh, sBh + (wn * 64 + f * 16) * 40 + ks * 16, 40);
                wmma::load_matrix_sync(bl, sBl + (wn * 64 + f * 16) * 40 + ks * 16, 40);
                #pragma unroll
                for (int mi = 0; mi < 2; mi++) {
                    wmma::mma_sync(acc[mi][f], ah[mi], bh, acc[mi][f]);
                    wmma::mma_sync(acc[mi][f], ah[mi], bl, acc[mi][f]);
                    wmma::mma_sync(acc[mi][f], al[mi], bh, acc[mi][f]);
                }
            }
        }
        __syncthreads();
    }

    float* sC = (float*)smraw;              // 128 x 128
    #pragma unroll
    for (int mi = 0; mi < 2; mi++)
        #pragma unroll
        for (int f = 0; f < 4; f++)
            wmma::store_matrix_sync(sC + (wm * 32 + mi * 16) * 128 + wn * 64 + f * 16,
                                    acc[mi][f], 128, wmma::mem_row_major);
    __syncthreads();

    // epilogue: 2 threads per row, 64 cols each
    const float* bias = (mode == 0) ? bq : (mode == 1) ? bk : bv;
    const int r   = tid >> 1;
    const int c0  = (tid & 1) * 64;
    const int tok = m0 + r;

    float vals[64];
    #pragma unroll
    for (int c = 0; c < 64; c++)
        vals[c] = sC[r * 128 + c0 + c] + bias[head * HD + c0 + c];

    if (mode < 2) {
        const float* wgt = (mode == 0) ? qn : kn;
        float ss = 0.f;
        #pragma unroll
        for (int c = 0; c < 64; c++) ss += vals[c] * vals[c];
        ss += __shfl_xor_sync(0xffffffffu, ss, 1);
        float rstd = rsqrtf(ss * (1.0f / HD) + EPSV);
        #pragma unroll
        for (int c = 0; c < 64; c++) vals[c] = vals[c] * rstd * wgt[c0 + c];

        if (tok < NV) {
            const float* rp = rope + (size_t)tok * 256 + c0 * 2;
            #pragma unroll
            for (int i = 0; i < 32; i++) {
                float4 r4 = *(const float4*)(rp + i * 4);
                float x0 = vals[2 * i], x1 = vals[2 * i + 1];
                vals[2 * i]     = r4.x * x0 + r4.y * x1;
                vals[2 * i + 1] = r4.z * x0 + r4.w * x1;
            }
        }
        if (mode == 0) {
            #pragma unroll
            for (int c = 0; c < 64; c++) vals[c] *= QSCALE;
        }
    }

    bf16* dsth = (mode == 0) ? g_Qh : (mode == 1) ? g_Kh : g_Vh;
    bf16* dstl = (mode == 0) ? g_Ql : (mode == 1) ? g_Kl : g_Vl;

    union { uint4 v; bf16 b[8]; } ph, pl;
    if (tok < NV) {
        int t = tok / 768, rem = tok - t * 768;
        int hh = rem >> 5, ww = rem & 31;
        int g   = (hh / 12) * 2 + (ww >> 4);
        int pos = t * 192 + (hh % 12) * 16 + (ww & 15);
        size_t off = ((size_t)((g * NHEADS + head) * LSEQ + pos)) * HD + c0;
        #pragma unroll
        for (int u = 0; u < 8; u++) {
            #pragma unroll
            for (int j = 0; j < 8; j++) split2(vals[u * 8 + j], ph.b[j], pl.b[j]);
            *(uint4*)(dsth + off + u * 8) = ph.v;
            *(uint4*)(dstl + off + u * 8) = pl.v;
        }
    } else {
        int pos = LVG + (tok - NV);
        #pragma unroll
        for (int u = 0; u < 8; u++) {
            #pragma unroll
            for (int j = 0; j < 8; j++) split2(vals[u * 8 + j], ph.b[j], pl.b[j]);
            #pragma unroll
            for (int g = 0; g < NG; g++) {
                size_t off = ((size_t)((g * NHEADS + head) * LSEQ + pos)) * HD + c0;
                *(uint4*)(dsth + off + u * 8) = ph.v;
                *(uint4*)(dstl + off + u * 8) = pl.v;
            }
        }
    }
}

// ---------------------------------------------------------------------------
// Attention: single-pass online softmax, raw mma.sync m16n8k16, bf16x3.
// BM=128 (8 warps x m16), BN=64 keys/tile, HD=128. grid = (13, 16, 4)
// ---------------------------------------------------------------------------
#define KSTR 136
#define ATT_SMEM ((128 * KSTR * 2 + 64 * KSTR * 4) * 2)   // 139,264 B

__global__ __launch_bounds__(256, 1) void attn_kernel()
{
    extern __shared__ char smraw[];
    bf16* sQh = (bf16*)smraw;               // 128 x 136
    bf16* sQl = sQh + 128 * KSTR;
    bf16* sKh = sQl + 128 * KSTR;           // 64 x 136
    bf16* sKl = sKh + 64 * KSTR;
    bf16* sVh = sKl + 64 * KSTR;
    bf16* sVl = sVh + 64 * KSTR;

    const int tid  = threadIdx.x;
    const int lane = tid & 31;
    const int w    = tid >> 5;
    const int q0   = blockIdx.x * 128;
    const int h    = blockIdx.y;
    const int g    = blockIdx.z;
    const size_t base = (size_t)(g * NHEADS + h) * LSEQ * HD;
    const bf16 *Qh = g_Qh + base, *Ql = g_Ql + base;
    const bf16 *Kh = g_Kh + base, *Kl = g_Kl + base;
    const bf16 *Vh = g_Vh + base, *Vl = g_Vl + base;

    // load Q tile
    #pragma unroll
    for (int i = 0; i < 8; i++) {
        int idx = tid + i * 256;
        int r = idx >> 4, cu = (idx & 15) << 3;
        size_t go = (size_t)(q0 + r) * HD + cu;
        *(uint4*)(sQh + r * KSTR + cu) = *(const uint4*)(Qh + go);
        *(uint4*)(sQl + r * KSTR + cu) = *(const uint4*)(Ql + go);
    }

    float m0 = -1e30f, m1 = -1e30f, l0 = 0.f, l1 = 0.f;
    float o[16][4];
    #pragma unroll
    for (int d = 0; d < 16; d++)
        #pragma unroll
        for (int j = 0; j < 4; j++) o[d][j] = 0.f;

    const int grp = lane >> 3, l7 = lane & 7;
    // A-operand (Q) ldmatrix pattern
    const int a_row  = w * 16 + ((grp & 1) << 3) + l7;
    const int a_col8 = (grp >> 1) << 3;
    const uint32_t qoffh = smem_u32(sQh) + (a_row * KSTR + a_col8) * 2;
    const uint32_t qoffl = smem_u32(sQl) + (a_row * KSTR + a_col8) * 2;
    // B-operand (K) pattern: rows = n, cols = k
    const int b_rowoff = ((grp >> 1) << 3) + l7;
    const int b_col8   = (grp & 1) << 3;
    // V (trans) pattern: rows = k, cols = d
    const int v_rowoff = ((grp & 1) << 3) + l7;
    const int v_col8   = (grp >> 1) << 3;
    const uint32_t kbh = smem_u32(sKh), kbl = smem_u32(sKl);
    const uint32_t vbh = smem_u32(sVh), vbl = smem_u32(sVl);

    __syncthreads();

    for (int kt = 0; kt < LSEQ; kt += 64) {
        // load K/V tile (64 x 128 bf16 x4 tensors)
        #pragma unroll
        for (int i = 0; i < 4; i++) {
            int idx = tid + i * 256;
            int r = idx >> 4, cu = (idx & 15) << 3;
            size_t go = (size_t)(kt + r) * HD + cu;
            int so = r * KSTR + cu;
            *(uint4*)(sKh + so) = *(const uint4*)(Kh + go);
            *(uint4*)(sKl + so) = *(const uint4*)(Kl + go);
            *(uint4*)(sVh + so) = *(const uint4*)(Vh + go);
            *(uint4*)(sVl + so) = *(const uint4*)(Vl + go);
        }
        __syncthreads();

        // ---- S = Q K^T (16 x 64 per warp) ----
        float sacc[8][4];
        #pragma unroll
        for (int n = 0; n < 8; n++)
            #pragma unroll
            for (int j = 0; j < 4; j++) sacc[n][j] = 0.f;

        #pragma unroll
        for (int kc = 0; kc < 8; kc++) {
            uint32_t qh[4], ql[4];
            ldsm4(qh, qoffh + kc * 32);     // 16 bf16 = 32 bytes
            ldsm4(ql, qoffl + kc * 32);
            #pragma unroll
            for (int np = 0; np < 4; np++) {
                uint32_t koff = ((np * 16 + b_rowoff) * KSTR + kc * 16 + b_col8) * 2;
                uint32_t kh4[4], kl4[4];
                ldsm4(kh4, kbh + koff);
                ldsm4(kl4, kbl + koff);
                mma_bf16(sacc[2*np],   qh, kh4[0], kh4[1]);
                mma_bf16(sacc[2*np],   qh, kl4[0], kl4[1]);
                mma_bf16(sacc[2*np],   ql, kh4[0], kh4[1]);
                mma_bf16(sacc[2*np+1], qh, kh4[2], kh4[3]);
                mma_bf16(sacc[2*np+1], qh, kl4[2], kl4[3]);
                mma_bf16(sacc[2*np+1], ql, kh4[2], kh4[3]);
            }
        }

        // ---- online softmax update ----
        float mt0 = -1e30f, mt1 = -1e30f;
        #pragma unroll
        for (int n = 0; n < 8; n++) {
            mt0 = fmaxf(mt0, fmaxf(sacc[n][0], sacc[n][1]));
            mt1 = fmaxf(mt1, fmaxf(sacc[n][2], sacc[n][3]));
        }
        mt0 = fmaxf(mt0, __shfl_xor_sync(0xffffffffu, mt0, 1));
        mt0 = fmaxf(mt0, __shfl_xor_sync(0xffffffffu, mt0, 2));
        mt1 = fmaxf(mt1, __shfl_xor_sync(0xffffffffu, mt1, 1));
        mt1 = fmaxf(mt1, __shfl_xor_sync(0xffffffffu, mt1, 2));
        float mn0 = fmaxf(m0, mt0), mn1 = fmaxf(m1, mt1);
        float al0 = __expf(m0 - mn0), al1 = __expf(m1 - mn1);
        m0 = mn0; m1 = mn1;

        float ls0 = 0.f, ls1 = 0.f;
        uint32_t pah[8][2], pal[8][2];
        #pragma unroll
        for (int n = 0; n < 8; n++) {
            float p0 = __expf(sacc[n][0] - mn0), p1 = __expf(sacc[n][1] - mn0);
            float p2 = __expf(sacc[n][2] - mn1), p3 = __expf(sacc[n][3] - mn1);
            ls0 += p0 + p1; ls1 += p2 + p3;
            bf16 h0, e0, h1, e1, h2, e2, h3, e3;
            split2(p0, h0, e0); split2(p1, h1, e1);
            split2(p2, h2, e2); split2(p3, h3, e3);
            pah[n][0] = pack2(h0, h1); pal[n][0] = pack2(e0, e1);
            pah[n][1] = pack2(h2, h3); pal[n][1] = pack2(e2, e3);
        }
        l0 = l0 * al0 + ls0;
        l1 = l1 * al1 + ls1;
        #pragma unroll
        for (int d = 0; d < 16; d++) {
            o[d][0] *= al0; o[d][1] *= al0;
            o[d][2] *= al1; o[d][3] *= al1;
        }

        // ---- O += P V ----
        #pragma unroll
        for (int kc = 0; kc < 4; kc++) {
            uint32_t ah[4] = { pah[2*kc][0], pah[2*kc][1], pah[2*kc+1][0], pah[2*kc+1][1] };
            uint32_t alo[4] = { pal[2*kc][0], pal[2*kc][1], pal[2*kc+1][0], pal[2*kc+1][1] };
            #pragma unroll
            for (int dp = 0; dp < 8; dp++) {
                uint32_t voff = ((kc * 16 + v_rowoff) * KSTR + dp * 16 + v_col8) * 2;
                uint32_t vh4[4], vl4[4];
                ldsm4t(vh4, vbh + voff);
                ldsm4t(vl4, vbl + voff);
                mma_bf16(o[2*dp],   ah,  vh4[0], vh4[1]);
                mma_bf16(o[2*dp],   ah,  vl4[0], vl4[1]);
                mma_bf16(o[2*dp],   alo, vh4[0], vh4[1]);
                mma_bf16(o[2*dp+1], ah,  vh4[2], vh4[3]);
                mma_bf16(o[2*dp+1], ah,  vl4[2], vl4[3]);
                mma_bf16(o[2*dp+1], alo, vh4[2], vh4[3]);
            }
        }
        __syncthreads();
    }

    // ---- finalize ----
    l0 += __shfl_xor_sync(0xffffffffu, l0, 1);
    l0 += __shfl_xor_sync(0xffffffffu, l0, 2);
    l1 += __shfl_xor_sync(0xffffffffu, l1, 1);
    l1 += __shfl_xor_sync(0xffffffffu, l1, 2);
    float inv0 = 1.f / l0, inv1 = 1.f / l1;

    int r0 = q0 + w * 16 + (lane >> 2);
    int r1 = r0 + 8;
    int cb = h * HD + (lane & 3) * 2;
    float* O0 = g_OG + (size_t)(g * LSEQ + r0) * CDIM + cb;
    float* O1 = g_OG + (size_t)(g * LSEQ + r1) * CDIM + cb;
    #pragma unroll
    for (int d = 0; d < 16; d++) {
        float2 v0 = { o[d][0] * inv0, o[d][1] * inv0 };
        float2 v1 = { o[d][2] * inv1, o[d][3] * inv1 };
        *(float2*)(O0 + d * 8) = v0;
        *(float2*)(O1 + d * 8) = v1;
    }
}

// ---------------------------------------------------------------------------
// Ungroup
// ---------------------------------------------------------------------------
__global__ __launch_bounds__(256) void ungroup_kernel()
{
    int i = blockIdx.x * 256 + threadIdx.x;
    if (i >= NTOK * CDIM / 4) return;
    int tok = i >> 9;
    int c4  = (i & 511) << 2;
    float4 res;
    if (tok < NV) {
        int t = tok / 768, rem = tok - t * 768;
        int hh = rem >> 5, ww = rem & 31;
        int g   = (hh / 12) * 2 + (ww >> 4);
        int pos = t * 192 + (hh % 12) * 16 + (ww & 15);
        res = *(const float4*)(g_OG + ((size_t)(g * LSEQ + pos)) * CDIM + c4);
    } else {
        int pos = LVG + tok - NV;
        float4 a = *(const float4*)(g_OG + ((size_t)(0 * LSEQ + pos)) * CDIM + c4);
        float4 b = *(const float4*)(g_OG + ((size_t)(1 * LSEQ + pos)) * CDIM + c4);
        float4 c = *(const float4*)(g_OG + ((size_t)(2 * LSEQ + pos)) * CDIM + c4);
        float4 d = *(const float4*)(g_OG + ((size_t)(3 * LSEQ + pos)) * CDIM + c4);
        res.x = (a.x + b.x + c.x + d.x) * 0.25f;
        res.y = (a.y + b.y + c.y + d.y) * 0.25f;
        res.z = (a.z + b.z + c.z + d.z) * 0.25f;
        res.w = (a.w + b.w + c.w + d.w) * 0.25f;
    }
    *(float4*)(g_X + (size_t)tok * CDIM + c4) = res;
}

// ---------------------------------------------------------------------------
// Output GEMM: BM=128, BN=128, warp tile 32x64. out = X @ Wo^T + bo
// ---------------------------------------------------------------------------
__global__ __launch_bounds__(256) void out_gemm_kernel(
    const float* __restrict__ Wo, const float* __restrict__ bo,
    float* __restrict__ out)
{
    extern __shared__ char smraw[];
    bf16* sAh = (bf16*)smraw;
    bf16* sAl = sAh + 128 * 40;
    bf16* sBh = sAl + 128 * 40;
    bf16* sBl = sBh + 128 * 40;

    const int tid  = threadIdx.x;
    const int w    = tid >> 5;
    const int wm   = w >> 1;
    const int wn   = w & 1;
    const int head = blockIdx.y;
    const int m0   = blockIdx.x * 128;

    FragC acc[2][4];
    #pragma unroll
    for (int mi = 0; mi < 2; mi++)
        #pragma unroll
        for (int f = 0; f < 4; f++) wmma::fill_fragment(acc[mi][f], 0.0f);

    for (int kt = 0; kt < CDIM; kt += 32) {
        #pragma unroll
        for (int i = 0; i < 4; i++) {
            int idx = tid + i * 256;
            int r = idx >> 3, c4 = (idx & 7) << 2;
            float4 v = *(const float4*)(g_X + (size_t)(m0 + r) * CDIM + kt + c4);
            int o = r * 40 + c4;
            split2(v.x, sAh[o+0], sAl[o+0]); split2(v.y, sAh[o+1], sAl[o+1]);
            split2(v.z, sAh[o+2], sAl[o+2]); split2(v.w, sAh[o+3], sAl[o+3]);
            float4 b = *(const float4*)(Wo + (size_t)(head * HD + r) * CDIM + kt + c4);
            split2(b.x, sBh[o+0], sBl[o+0]); split2(b.y, sBh[o+1], sBl[o+1]);
            split2(b.z, sBh[o+2], sBl[o+2]); split2(b.w, sBh[o+3], sBl[o+3]);
        }
        __syncthreads();
        #pragma unroll
        for (int ks = 0; ks < 2; ks++) {
            FragA ah[2], al[2];
            #pragma unroll
            for (int mi = 0; mi < 2; mi++) {
                wmma::load_matrix_sync(ah[mi], sAh + (wm * 32 + mi * 16) * 40 + ks * 16, 40);
                wmma::load_matrix_sync(al[mi], sAl + (wm * 32 + mi * 16) * 40 + ks * 16, 40);
            }
            #pragma unroll
            for (int f = 0; f < 4; f++) {
                FragBc bh, bl;
                wmma::load_matrix_sync(bh, sBh + (wn * 64 + f * 16) * 40 + ks * 16, 40);
                wmma::load_matrix_sync(bl, sBl + (wn * 64 + f * 16) * 40 + ks * 16, 40);
                #pragma unroll
                for (int mi = 0; mi < 2; mi++) {
                    wmma::mma_sync(acc[mi][f], ah[mi], bh, acc[mi][f]);
                    wmma::mma_sync(acc[mi][f], ah[mi], bl, acc[mi][f]);
                    wmma::mma_sync(acc[mi][f], al[mi], bh, acc[mi][f]);
                }
            }
        }
        __syncthreads();
    }

    float* sC = (float*)smraw;
    #pragma unroll
    for (int mi = 0; mi < 2; mi++)
        #pragma unroll
        for (int f = 0; f < 4; f++)
            wmma::store_matrix_sync(sC + (wm * 32 + mi * 16) * 128 + wn * 64 + f * 16,
                                    acc[mi][f], 128, wmma::mem_row_major);
    __syncthreads();

    const int r  = tid >> 1;
    const int c0 = (tid & 1) * 64;
    const int tok = m0 + r;
    float* d = out + (size_t)tok * CDIM + head * HD + c0;
    #pragma unroll
    for (int u = 0; u < 16; u++) {
        float4 v;
        v.x = sC[r * 128 + c0 + u*4 + 0] + bo[head * HD + c0 + u*4 + 0];
        v.y = sC[r * 128 + c0 + u*4 + 1] + bo[head * HD + c0 + u*4 + 1];
        v.z = sC[r * 128 + c0 + u*4 + 2] + bo[head * HD + c0 + u*4 + 2];
        v.w = sC[r * 128 + c0 + u*4 + 3] + bo[head * HD + c0 + u*4 + 3];
        *(float4*)(d + u * 4) = v;
    }
}

// ---------------------------------------------------------------------------
extern "C" void kernel_launch(void* const* d_in, const int* in_sizes, int n_in,
                              void* d_out, int out_size)
{
    const float* vis  = (const float*)d_in[0];
    const float* txt  = (const float*)d_in[1];
    const float* rope = (const float*)d_in[2];
    const float* Wq   = (const float*)d_in[3];
    const float* bq   = (const float*)d_in[4];
    const float* Wk   = (const float*)d_in[5];
    const float* bk   = (const float*)d_in[6];
    const float* Wv   = (const float*)d_in[7];
    const float* bv   = (const float*)d_in[8];
    const float* qn   = (const float*)d_in[9];
    const float* kn   = (const float*)d_in[10];
    const float* Wo   = (const float*)d_in[11];
    const float* bo   = (const float*)d_in[12];
    float* out = (float*)d_out;
    (void)in_sizes; (void)n_in; (void)out_size;

    static bool attr_done = false;
    if (!attr_done) {
        cudaFuncSetAttribute(qkv_gemm_kernel, cudaFuncAttributeMaxDynamicSharedMemorySize, GEMM_SMEM);
        cudaFuncSetAttribute(out_gemm_kernel, cudaFuncAttributeMaxDynamicSharedMemorySize, GEMM_SMEM);
        cudaFuncSetAttribute(attn_kernel,     cudaFuncAttributeMaxDynamicSharedMemorySize, ATT_SMEM);
        attr_done = true;
    }

    dim3 gq(49, 16, 3);
    qkv_gemm_kernel<<<gq, 256, GEMM_SMEM>>>(vis, txt, rope, Wq, bq, Wk, bk, Wv, bv, qn, kn);

    dim3 ga(13, 16, 4);
    attn_kernel<<<ga, 256, ATT_SMEM>>>();

    ungroup_kernel<<<(NTOK * CDIM / 4 + 255) / 256, 256>>>();

    dim3 go(49, 16, 1);
    out_gemm_kernel<<<go, 256, GEMM_SMEM>>>(Wo, bo, out);
}

// round 7
// speedup vs baseline: 1.7296x; 1.2757x over previous
#include <cuda_runtime.h>
#include <cuda_bf16.h>
#include <mma.h>
#include <cstdint>

using namespace nvcuda;
typedef __nv_bfloat16 bf16;

#define NHEADS 16
#define HD     128
#define CDIM   2048
#define NV     6144
#define LT     128
#define NTOK   6272
#define NG     4
#define LVG    1536
#define LSEQ   1664
#define EPSV   1e-6f
#define QSCALE 0.08838834764831845f

// ---------------------------------------------------------------------------
// Scratch
// ---------------------------------------------------------------------------
#define QKV_ELEMS ((size_t)NG * NHEADS * LSEQ * HD)
__device__ bf16 g_Qh[QKV_ELEMS], g_Ql[QKV_ELEMS];
__device__ bf16 g_Kh[QKV_ELEMS], g_Kl[QKV_ELEMS];
__device__ bf16 g_Vh[QKV_ELEMS], g_Vl[QKV_ELEMS];
__device__ float g_OG[(size_t)NG * LSEQ * CDIM];
// pre-split operands
__device__ bf16 g_XAh[(size_t)NTOK * CDIM], g_XAl[(size_t)NTOK * CDIM];   // input embeds
__device__ bf16 g_XOh[(size_t)NTOK * CDIM], g_XOl[(size_t)NTOK * CDIM];   // attn output
__device__ bf16 g_Wqh[(size_t)CDIM * CDIM], g_Wql[(size_t)CDIM * CDIM];
__device__ bf16 g_Wkh[(size_t)CDIM * CDIM], g_Wkl[(size_t)CDIM * CDIM];
__device__ bf16 g_Wvh[(size_t)CDIM * CDIM], g_Wvl[(size_t)CDIM * CDIM];
__device__ bf16 g_Woh[(size_t)CDIM * CDIM], g_Wol[(size_t)CDIM * CDIM];

__device__ __forceinline__ void split2(float x, bf16& h, bf16& l) {
    h = __float2bfloat16(x);
    l = __float2bfloat16(x - __bfloat162float(h));
}
__device__ __forceinline__ uint32_t pack2(bf16 a, bf16 b) {
    __nv_bfloat162 t; t.x = a; t.y = b;
    return *reinterpret_cast<uint32_t*>(&t);
}
__device__ __forceinline__ uint32_t smem_u32(const void* p) {
    return (uint32_t)__cvta_generic_to_shared(p);
}
__device__ __forceinline__ void cp16(uint32_t dst, const void* src) {
    asm volatile("cp.async.cg.shared.global [%0], [%1], 16;" :: "r"(dst), "l"(src));
}
__device__ __forceinline__ void cp_commit() {
    asm volatile("cp.async.commit_group;");
}
__device__ __forceinline__ void cp_wait1() {
    asm volatile("cp.async.wait_group 1;");
}
__device__ __forceinline__ void ldsm4(uint32_t* r, uint32_t addr) {
    asm volatile("ldmatrix.sync.aligned.m8n8.x4.shared.b16 {%0,%1,%2,%3},[%4];"
                 : "=r"(r[0]), "=r"(r[1]), "=r"(r[2]), "=r"(r[3]) : "r"(addr));
}
__device__ __forceinline__ void ldsm4t(uint32_t* r, uint32_t addr) {
    asm volatile("ldmatrix.sync.aligned.m8n8.x4.trans.shared.b16 {%0,%1,%2,%3},[%4];"
                 : "=r"(r[0]), "=r"(r[1]), "=r"(r[2]), "=r"(r[3]) : "r"(addr));
}
__device__ __forceinline__ void mma_bf16(float* c, const uint32_t* a,
                                         uint32_t b0, uint32_t b1) {
    asm volatile(
        "mma.sync.aligned.m16n8k16.row.col.f32.bf16.bf16.f32 "
        "{%0,%1,%2,%3},{%4,%5,%6,%7},{%8,%9},{%0,%1,%2,%3};"
        : "+f"(c[0]), "+f"(c[1]), "+f"(c[2]), "+f"(c[3])
        : "r"(a[0]), "r"(a[1]), "r"(a[2]), "r"(a[3]), "r"(b0), "r"(b1));
}

typedef wmma::fragment<wmma::matrix_a, 16, 16, 16, bf16, wmma::row_major>  FragA;
typedef wmma::fragment<wmma::matrix_b, 16, 16, 16, bf16, wmma::col_major>  FragBc;
typedef wmma::fragment<wmma::accumulator, 16, 16, 16, float>               FragC;

// GEMM smem: stage = {Ah,Al,Bh,Bl} each 128x40 bf16; 2 stages = 81,920 B
#define STR   40
#define ARR   (128 * STR)
#define STAGE (4 * ARR)
#define GEMM_SMEM (2 * STAGE * 2)

// ---------------------------------------------------------------------------
// split: fp32 -> bf16 hi/lo  (grid-stride over float4)
// ---------------------------------------------------------------------------
__global__ __launch_bounds__(256) void split_kernel(
    const float* __restrict__ src, bf16* __restrict__ dh, bf16* __restrict__ dl,
    int n4)
{
    int i = blockIdx.x * 256 + threadIdx.x;
    if (i >= n4) return;
    float4 v = ((const float4*)src)[i];
    union { uint2 u; bf16 b[4]; } h, l;
    split2(v.x, h.b[0], l.b[0]); split2(v.y, h.b[1], l.b[1]);
    split2(v.z, h.b[2], l.b[2]); split2(v.w, h.b[3], l.b[3]);
    ((uint2*)dh)[i] = h.u;
    ((uint2*)dl)[i] = l.u;
}

// ---------------------------------------------------------------------------
// Core pipelined bf16x3 GEMM tile loop. Computes 128x128 fp32 tile in acc.
// Each thread copies rows r and r+64 of each of the 4 arrays (8 cp16/stage).
// ---------------------------------------------------------------------------
__device__ __forceinline__ void gemm_tile(
    const bf16* __restrict__ Ah, const bf16* __restrict__ Al, size_t a_row0,
    const bf16* __restrict__ Bh, const bf16* __restrict__ Bl, size_t b_row0,
    bf16* smbase, int tid, int wm, int wn, FragC acc[2][4])
{
    const int r  = tid >> 2;                 // 0..63
    const int c8 = (tid & 3) << 3;           // 0,8,16,24
    const size_t aoff  = (a_row0 + r) * CDIM + c8;
    const size_t aoff2 = aoff + (size_t)64 * CDIM;
    const size_t boff  = (b_row0 + r) * CDIM + c8;
    const size_t boff2 = boff + (size_t)64 * CDIM;
    const uint32_t sbase = smem_u32(smbase);
    const uint32_t so  = sbase + (r * STR + c8) * 2;
    const uint32_t so2 = so + 64 * STR * 2;

    // prologue: stage 0, kt = 0
    cp16(so,                Ah + aoff);
    cp16(so2,               Ah + aoff2);
    cp16(so  + ARR * 2,     Al + aoff);
    cp16(so2 + ARR * 2,     Al + aoff2);
    cp16(so  + 2 * ARR * 2, Bh + boff);
    cp16(so2 + 2 * ARR * 2, Bh + boff2);
    cp16(so  + 3 * ARR * 2, Bl + boff);
    cp16(so2 + 3 * ARR * 2, Bl + boff2);
    cp_commit();

    const int NIT = CDIM / 32;
    for (int it = 0; it < NIT; it++) {
        if (it + 1 < NIT) {
            uint32_t sn  = so  + ((it + 1) & 1) * STAGE * 2;
            uint32_t sn2 = so2 + ((it + 1) & 1) * STAGE * 2;
            int kt = (it + 1) * 32;
            cp16(sn,                Ah + aoff  + kt);
            cp16(sn2,               Ah + aoff2 + kt);
            cp16(sn  + ARR * 2,     Al + aoff  + kt);
            cp16(sn2 + ARR * 2,     Al + aoff2 + kt);
            cp16(sn  + 2 * ARR * 2, Bh + boff  + kt);
            cp16(sn2 + 2 * ARR * 2, Bh + boff2 + kt);
            cp16(sn  + 3 * ARR * 2, Bl + boff  + kt);
            cp16(sn2 + 3 * ARR * 2, Bl + boff2 + kt);
        }
        cp_commit();
        cp_wait1();
        __syncthreads();

        bf16* st  = smbase + (it & 1) * STAGE;
        bf16* sAh = st;
        bf16* sAl = st + ARR;
        bf16* sBh = st + 2 * ARR;
        bf16* sBl = st + 3 * ARR;
        #pragma unroll
        for (int ks = 0; ks < 2; ks++) {
            FragA ah[2], al[2];
            #pragma unroll
            for (int mi = 0; mi < 2; mi++) {
                wmma::load_matrix_sync(ah[mi], sAh + (wm * 32 + mi * 16) * STR + ks * 16, STR);
                wmma::load_matrix_sync(al[mi], sAl + (wm * 32 + mi * 16) * STR + ks * 16, STR);
            }
            #pragma unroll
            for (int f = 0; f < 4; f++) {
                FragBc bh, bl;
                wmma::load_matrix_sync(bh, sBh + (wn * 64 + f * 16) * STR + ks * 16, STR);
                wmma::load_matrix_sync(bl, sBl + (wn * 64 + f * 16) * STR + ks * 16, STR);
                #pragma unroll
                for (int mi = 0; mi < 2; mi++) {
                    wmma::mma_sync(acc[mi][f], ah[mi], bh, acc[mi][f]);
                    wmma::mma_sync(acc[mi][f], ah[mi], bl, acc[mi][f]);
                    wmma::mma_sync(acc[mi][f], al[mi], bh, acc[mi][f]);
                }
            }
        }
        __syncthreads();
    }
}

// ---------------------------------------------------------------------------
// QKV GEMM + fused epilogue.  grid = (49, 16, 3)
// ---------------------------------------------------------------------------
__global__ __launch_bounds__(256) void qkv_gemm_kernel(
    const float* __restrict__ rope,
    const float* __restrict__ bq, const float* __restrict__ bk,
    const float* __restrict__ bv,
    const float* __restrict__ qn, const float* __restrict__ kn)
{
    extern __shared__ char smraw[];
    bf16* smbase = (bf16*)smraw;

    const int tid  = threadIdx.x;
    const int w    = tid >> 5;
    const int wm   = w >> 1;
    const int wn   = w & 1;
    const int mode = blockIdx.z;
    const int head = blockIdx.y;
    const int m0   = blockIdx.x * 128;

    const bf16* Wh = (mode == 0) ? g_Wqh : (mode == 1) ? g_Wkh : g_Wvh;
    const bf16* Wl = (mode == 0) ? g_Wql : (mode == 1) ? g_Wkl : g_Wvl;

    FragC acc[2][4];
    #pragma unroll
    for (int mi = 0; mi < 2; mi++)
        #pragma unroll
        for (int f = 0; f < 4; f++) wmma::fill_fragment(acc[mi][f], 0.0f);

    gemm_tile(g_XAh, g_XAl, (size_t)m0, Wh, Wl, (size_t)head * HD,
              smbase, tid, wm, wn, acc);

    float* sC = (float*)smraw;              // 128 x 128 = 64 KB
    #pragma unroll
    for (int mi = 0; mi < 2; mi++)
        #pragma unroll
        for (int f = 0; f < 4; f++)
            wmma::store_matrix_sync(sC + (wm * 32 + mi * 16) * 128 + wn * 64 + f * 16,
                                    acc[mi][f], 128, wmma::mem_row_major);
    __syncthreads();

    // epilogue: 2 threads per row, 64 cols each
    const float* bias = (mode == 0) ? bq : (mode == 1) ? bk : bv;
    const int r   = tid >> 1;
    const int c0  = (tid & 1) * 64;
    const int tok = m0 + r;

    float vals[64];
    #pragma unroll
    for (int c = 0; c < 64; c++)
        vals[c] = sC[r * 128 + c0 + c] + bias[head * HD + c0 + c];

    if (mode < 2) {
        const float* wgt = (mode == 0) ? qn : kn;
        float ss = 0.f;
        #pragma unroll
        for (int c = 0; c < 64; c++) ss += vals[c] * vals[c];
        ss += __shfl_xor_sync(0xffffffffu, ss, 1);
        float rstd = rsqrtf(ss * (1.0f / HD) + EPSV);
        #pragma unroll
        for (int c = 0; c < 64; c++) vals[c] = vals[c] * rstd * wgt[c0 + c];

        if (tok < NV) {
            const float* rp = rope + (size_t)tok * 256 + c0 * 2;
            #pragma unroll
            for (int i = 0; i < 32; i++) {
                float4 r4 = *(const float4*)(rp + i * 4);
                float x0 = vals[2 * i], x1 = vals[2 * i + 1];
                vals[2 * i]     = r4.x * x0 + r4.y * x1;
                vals[2 * i + 1] = r4.z * x0 + r4.w * x1;
            }
        }
        if (mode == 0) {
            #pragma unroll
            for (int c = 0; c < 64; c++) vals[c] *= QSCALE;
        }
    }

    bf16* dsth = (mode == 0) ? g_Qh : (mode == 1) ? g_Kh : g_Vh;
    bf16* dstl = (mode == 0) ? g_Ql : (mode == 1) ? g_Kl : g_Vl;

    union { uint4 v; bf16 b[8]; } ph, pl;
    if (tok < NV) {
        int t = tok / 768, rem = tok - t * 768;
        int hh = rem >> 5, ww = rem & 31;
        int g   = (hh / 12) * 2 + (ww >> 4);
        int pos = t * 192 + (hh % 12) * 16 + (ww & 15);
        size_t off = ((size_t)((g * NHEADS + head) * LSEQ + pos)) * HD + c0;
        #pragma unroll
        for (int u = 0; u < 8; u++) {
            #pragma unroll
            for (int j = 0; j < 8; j++) split2(vals[u * 8 + j], ph.b[j], pl.b[j]);
            *(uint4*)(dsth + off + u * 8) = ph.v;
            *(uint4*)(dstl + off + u * 8) = pl.v;
        }
    } else {
        int pos = LVG + (tok - NV);
        #pragma unroll
        for (int u = 0; u < 8; u++) {
            #pragma unroll
            for (int j = 0; j < 8; j++) split2(vals[u * 8 + j], ph.b[j], pl.b[j]);
            #pragma unroll
            for (int g = 0; g < NG; g++) {
                size_t off = ((size_t)((g * NHEADS + head) * LSEQ + pos)) * HD + c0;
                *(uint4*)(dsth + off + u * 8) = ph.v;
                *(uint4*)(dstl + off + u * 8) = pl.v;
            }
        }
    }
}

// ---------------------------------------------------------------------------
// Attention: single-pass online softmax, raw mma.sync, bf16x3.
// grid = (13, 16, 4)
// ---------------------------------------------------------------------------
#define KSTR 136
#define ATT_SMEM ((128 * KSTR * 2 + 64 * KSTR * 4) * 2)

__global__ __launch_bounds__(256, 1) void attn_kernel()
{
    extern __shared__ char smraw[];
    bf16* sQh = (bf16*)smraw;
    bf16* sQl = sQh + 128 * KSTR;
    bf16* sKh = sQl + 128 * KSTR;
    bf16* sKl = sKh + 64 * KSTR;
    bf16* sVh = sKl + 64 * KSTR;
    bf16* sVl = sVh + 64 * KSTR;

    const int tid  = threadIdx.x;
    const int lane = tid & 31;
    const int w    = tid >> 5;
    const int q0   = blockIdx.x * 128;
    const int h    = blockIdx.y;
    const int g    = blockIdx.z;
    const size_t base = (size_t)(g * NHEADS + h) * LSEQ * HD;
    const bf16 *Qh = g_Qh + base, *Ql = g_Ql + base;
    const bf16 *Kh = g_Kh + base, *Kl = g_Kl + base;
    const bf16 *Vh = g_Vh + base, *Vl = g_Vl + base;

    #pragma unroll
    for (int i = 0; i < 8; i++) {
        int idx = tid + i * 256;
        int r = idx >> 4, cu = (idx & 15) << 3;
        size_t go = (size_t)(q0 + r) * HD + cu;
        *(uint4*)(sQh + r * KSTR + cu) = *(const uint4*)(Qh + go);
        *(uint4*)(sQl + r * KSTR + cu) = *(const uint4*)(Ql + go);
    }

    float m0 = -1e30f, m1 = -1e30f, l0 = 0.f, l1 = 0.f;
    float o[16][4];
    #pragma unroll
    for (int d = 0; d < 16; d++)
        #pragma unroll
        for (int j = 0; j < 4; j++) o[d][j] = 0.f;

    const int grp = lane >> 3, l7 = lane & 7;
    const int a_row  = w * 16 + ((grp & 1) << 3) + l7;
    const int a_col8 = (grp >> 1) << 3;
    const uint32_t qoffh = smem_u32(sQh) + (a_row * KSTR + a_col8) * 2;
    const uint32_t qoffl = smem_u32(sQl) + (a_row * KSTR + a_col8) * 2;
    const int b_rowoff = ((grp >> 1) << 3) + l7;
    const int b_col8   = (grp & 1) << 3;
    const int v_rowoff = ((grp & 1) << 3) + l7;
    const int v_col8   = (grp >> 1) << 3;
    const uint32_t kbh = smem_u32(sKh), kbl = smem_u32(sKl);
    const uint32_t vbh = smem_u32(sVh), vbl = smem_u32(sVl);

    __syncthreads();

    for (int kt = 0; kt < LSEQ; kt += 64) {
        #pragma unroll
        for (int i = 0; i < 4; i++) {
            int idx = tid + i * 256;
            int r = idx >> 4, cu = (idx & 15) << 3;
            size_t go = (size_t)(kt + r) * HD + cu;
            int so = r * KSTR + cu;
            *(uint4*)(sKh + so) = *(const uint4*)(Kh + go);
            *(uint4*)(sKl + so) = *(const uint4*)(Kl + go);
            *(uint4*)(sVh + so) = *(const uint4*)(Vh + go);
            *(uint4*)(sVl + so) = *(const uint4*)(Vl + go);
        }
        __syncthreads();

        float sacc[8][4];
        #pragma unroll
        for (int n = 0; n < 8; n++)
            #pragma unroll
            for (int j = 0; j < 4; j++) sacc[n][j] = 0.f;

        #pragma unroll
        for (int kc = 0; kc < 8; kc++) {
            uint32_t qh[4], ql[4];
            ldsm4(qh, qoffh + kc * 32);
            ldsm4(ql, qoffl + kc * 32);
            #pragma unroll
            for (int np = 0; np < 4; np++) {
                uint32_t koff = ((np * 16 + b_rowoff) * KSTR + kc * 16 + b_col8) * 2;
                uint32_t kh4[4], kl4[4];
                ldsm4(kh4, kbh + koff);
                ldsm4(kl4, kbl + koff);
                mma_bf16(sacc[2*np],   qh, kh4[0], kh4[1]);
                mma_bf16(sacc[2*np],   qh, kl4[0], kl4[1]);
                mma_bf16(sacc[2*np],   ql, kh4[0], kh4[1]);
                mma_bf16(sacc[2*np+1], qh, kh4[2], kh4[3]);
                mma_bf16(sacc[2*np+1], qh, kl4[2], kl4[3]);
                mma_bf16(sacc[2*np+1], ql, kh4[2], kh4[3]);
            }
        }

        float mt0 = -1e30f, mt1 = -1e30f;
        #pragma unroll
        for (int n = 0; n < 8; n++) {
            mt0 = fmaxf(mt0, fmaxf(sacc[n][0], sacc[n][1]));
            mt1 = fmaxf(mt1, fmaxf(sacc[n][2], sacc[n][3]));
        }
        mt0 = fmaxf(mt0, __shfl_xor_sync(0xffffffffu, mt0, 1));
        mt0 = fmaxf(mt0, __shfl_xor_sync(0xffffffffu, mt0, 2));
        mt1 = fmaxf(mt1, __shfl_xor_sync(0xffffffffu, mt1, 1));
        mt1 = fmaxf(mt1, __shfl_xor_sync(0xffffffffu, mt1, 2));
        float mn0 = fmaxf(m0, mt0), mn1 = fmaxf(m1, mt1);
        float al0 = __expf(m0 - mn0), al1 = __expf(m1 - mn1);
        m0 = mn0; m1 = mn1;

        float ls0 = 0.f, ls1 = 0.f;
        uint32_t pah[8][2], pal[8][2];
        #pragma unroll
        for (int n = 0; n < 8; n++) {
            float p0 = __expf(sacc[n][0] - mn0), p1 = __expf(sacc[n][1] - mn0);
            float p2 = __expf(sacc[n][2] - mn1), p3 = __expf(sacc[n][3] - mn1);
            ls0 += p0 + p1; ls1 += p2 + p3;
            bf16 h0, e0, h1, e1, h2, e2, h3, e3;
            split2(p0, h0, e0); split2(p1, h1, e1);
            split2(p2, h2, e2); split2(p3, h3, e3);
            pah[n][0] = pack2(h0, h1); pal[n][0] = pack2(e0, e1);
            pah[n][1] = pack2(h2, h3); pal[n][1] = pack2(e2, e3);
        }
        l0 = l0 * al0 + ls0;
        l1 = l1 * al1 + ls1;
        #pragma unroll
        for (int d = 0; d < 16; d++) {
            o[d][0] *= al0; o[d][1] *= al0;
            o[d][2] *= al1; o[d][3] *= al1;
        }

        #pragma unroll
        for (int kc = 0; kc < 4; kc++) {
            uint32_t ah[4] = { pah[2*kc][0], pah[2*kc][1], pah[2*kc+1][0], pah[2*kc+1][1] };
            uint32_t alo[4] = { pal[2*kc][0], pal[2*kc][1], pal[2*kc+1][0], pal[2*kc+1][1] };
            #pragma unroll
            for (int dp = 0; dp < 8; dp++) {
                uint32_t voff = ((kc * 16 + v_rowoff) * KSTR + dp * 16 + v_col8) * 2;
                uint32_t vh4[4], vl4[4];
                ldsm4t(vh4, vbh + voff);
                ldsm4t(vl4, vbl + voff);
                mma_bf16(o[2*dp],   ah,  vh4[0], vh4[1]);
                mma_bf16(o[2*dp],   ah,  vl4[0], vl4[1]);
                mma_bf16(o[2*dp],   alo, vh4[0], vh4[1]);
                mma_bf16(o[2*dp+1], ah,  vh4[2], vh4[3]);
                mma_bf16(o[2*dp+1], ah,  vl4[2], vl4[3]);
                mma_bf16(o[2*dp+1], alo, vh4[2], vh4[3]);
            }
        }
        __syncthreads();
    }

    l0 += __shfl_xor_sync(0xffffffffu, l0, 1);
    l0 += __shfl_xor_sync(0xffffffffu, l0, 2);
    l1 += __shfl_xor_sync(0xffffffffu, l1, 1);
    l1 += __shfl_xor_sync(0xffffffffu, l1, 2);
    float inv0 = 1.f / l0, inv1 = 1.f / l1;

    int r0 = q0 + w * 16 + (lane >> 2);
    int r1 = r0 + 8;
    int cb = h * HD + (lane & 3) * 2;
    float* O0 = g_OG + (size_t)(g * LSEQ + r0) * CDIM + cb;
    float* O1 = g_OG + (size_t)(g * LSEQ + r1) * CDIM + cb;
    #pragma unroll
    for (int d = 0; d < 16; d++) {
        float2 v0 = { o[d][0] * inv0, o[d][1] * inv0 };
        float2 v1 = { o[d][2] * inv1, o[d][3] * inv1 };
        *(float2*)(O0 + d * 8) = v0;
        *(float2*)(O1 + d * 8) = v1;
    }
}

// ---------------------------------------------------------------------------
// Ungroup (writes bf16 hi/lo directly)
// ---------------------------------------------------------------------------
__global__ __launch_bounds__(256) void ungroup_kernel()
{
    int i = blockIdx.x * 256 + threadIdx.x;
    if (i >= NTOK * CDIM / 4) return;
    int tok = i >> 9;
    int c4  = (i & 511) << 2;
    float4 res;
    if (tok < NV) {
        int t = tok / 768, rem = tok - t * 768;
        int hh = rem >> 5, ww = rem & 31;
        int g   = (hh / 12) * 2 + (ww >> 4);
        int pos = t * 192 + (hh % 12) * 16 + (ww & 15);
        res = *(const float4*)(g_OG + ((size_t)(g * LSEQ + pos)) * CDIM + c4);
    } else {
        int pos = LVG + tok - NV;
        float4 a = *(const float4*)(g_OG + ((size_t)(0 * LSEQ + pos)) * CDIM + c4);
        float4 b = *(const float4*)(g_OG + ((size_t)(1 * LSEQ + pos)) * CDIM + c4);
        float4 c = *(const float4*)(g_OG + ((size_t)(2 * LSEQ + pos)) * CDIM + c4);
        float4 d = *(const float4*)(g_OG + ((size_t)(3 * LSEQ + pos)) * CDIM + c4);
        res.x = (a.x + b.x + c.x + d.x) * 0.25f;
        res.y = (a.y + b.y + c.y + d.y) * 0.25f;
        res.z = (a.z + b.z + c.z + d.z) * 0.25f;
        res.w = (a.w + b.w + c.w + d.w) * 0.25f;
    }
    union { uint2 u; bf16 b[4]; } h, l;
    split2(res.x, h.b[0], l.b[0]); split2(res.y, h.b[1], l.b[1]);
    split2(res.z, h.b[2], l.b[2]); split2(res.w, h.b[3], l.b[3]);
    ((uint2*)g_XOh)[i] = h.u;
    ((uint2*)g_XOl)[i] = l.u;
}

// ---------------------------------------------------------------------------
// Output GEMM.  grid = (49, 16)
// ---------------------------------------------------------------------------
__global__ __launch_bounds__(256) void out_gemm_kernel(
    const float* __restrict__ bo, float* __restrict__ out)
{
    extern __shared__ char smraw[];
    bf16* smbase = (bf16*)smraw;

    const int tid  = threadIdx.x;
    const int w    = tid >> 5;
    const int wm   = w >> 1;
    const int wn   = w & 1;
    const int head = blockIdx.y;
    const int m0   = blockIdx.x * 128;

    FragC acc[2][4];
    #pragma unroll
    for (int mi = 0; mi < 2; mi++)
        #pragma unroll
        for (int f = 0; f < 4; f++) wmma::fill_fragment(acc[mi][f], 0.0f);

    gemm_tile(g_XOh, g_XOl, (size_t)m0, g_Woh, g_Wol, (size_t)head * HD,
              smbase, tid, wm, wn, acc);

    float* sC = (float*)smraw;
    #pragma unroll
    for (int mi = 0; mi < 2; mi++)
        #pragma unroll
        for (int f = 0; f < 4; f++)
            wmma::store_matrix_sync(sC + (wm * 32 + mi * 16) * 128 + wn * 64 + f * 16,
                                    acc[mi][f], 128, wmma::mem_row_major);
    __syncthreads();

    const int r  = tid >> 1;
    const int c0 = (tid & 1) * 64;
    const int tok = m0 + r;
    float* d = out + (size_t)tok * CDIM + head * HD + c0;
    #pragma unroll
    for (int u = 0; u < 16; u++) {
        float4 v;
        v.x = sC[r * 128 + c0 + u*4 + 0] + bo[head * HD + c0 + u*4 + 0];
        v.y = sC[r * 128 + c0 + u*4 + 1] + bo[head * HD + c0 + u*4 + 1];
        v.z = sC[r * 128 + c0 + u*4 + 2] + bo[head * HD + c0 + u*4 + 2];
        v.w = sC[r * 128 + c0 + u*4 + 3] + bo[head * HD + c0 + u*4 + 3];
        *(float4*)(d + u * 4) = v;
    }
}

// ---------------------------------------------------------------------------
extern "C" void kernel_launch(void* const* d_in, const int* in_sizes, int n_in,
                              void* d_out, int out_size)
{
    const float* vis  = (const float*)d_in[0];
    const float* txt  = (const float*)d_in[1];
    const float* rope = (const float*)d_in[2];
    const float* Wq   = (const float*)d_in[3];
    const float* bq   = (const float*)d_in[4];
    const float* Wk   = (const float*)d_in[5];
    const float* bk   = (const float*)d_in[6];
    const float* Wv   = (const float*)d_in[7];
    const float* bv   = (const float*)d_in[8];
    const float* qn   = (const float*)d_in[9];
    const float* kn   = (const float*)d_in[10];
    const float* Wo   = (const float*)d_in[11];
    const float* bo   = (const float*)d_in[12];
    float* out = (float*)d_out;
    (void)in_sizes; (void)n_in; (void)out_size;

    cudaFuncSetAttribute(qkv_gemm_kernel, cudaFuncAttributeMaxDynamicSharedMemorySize, GEMM_SMEM);
    cudaFuncSetAttribute(out_gemm_kernel, cudaFuncAttributeMaxDynamicSharedMemorySize, GEMM_SMEM);
    cudaFuncSetAttribute(attn_kernel,     cudaFuncAttributeMaxDynamicSharedMemorySize, ATT_SMEM);

    // pre-split inputs and weights to bf16 hi/lo
    bf16* xh; bf16* xl;
    cudaGetSymbolAddress((void**)&xh, g_XAh);
    cudaGetSymbolAddress((void**)&xl, g_XAl);
    split_kernel<<<(NV * CDIM / 4 + 255) / 256, 256>>>(vis, xh, xl, NV * CDIM / 4);
    split_kernel<<<(LT * CDIM / 4 + 255) / 256, 256>>>(
        txt, xh + (size_t)NV * CDIM, xl + (size_t)NV * CDIM, LT * CDIM / 4);

    bf16 *wh, *wl;
    cudaGetSymbolAddress((void**)&wh, g_Wqh); cudaGetSymbolAddress((void**)&wl, g_Wql);
    split_kernel<<<(CDIM * CDIM / 4 + 255) / 256, 256>>>(Wq, wh, wl, CDIM * CDIM / 4);
    cudaGetSymbolAddress((void**)&wh, g_Wkh); cudaGetSymbolAddress((void**)&wl, g_Wkl);
    split_kernel<<<(CDIM * CDIM / 4 + 255) / 256, 256>>>(Wk, wh, wl, CDIM * CDIM / 4);
    cudaGetSymbolAddress((void**)&wh, g_Wvh); cudaGetSymbolAddress((void**)&wl, g_Wvl);
    split_kernel<<<(CDIM * CDIM / 4 + 255) / 256, 256>>>(Wv, wh, wl, CDIM * CDIM / 4);
    cudaGetSymbolAddress((void**)&wh, g_Woh); cudaGetSymbolAddress((void**)&wl, g_Wol);
    split_kernel<<<(CDIM * CDIM / 4 + 255) / 256, 256>>>(Wo, wh, wl, CDIM * CDIM / 4);

    dim3 gq(49, 16, 3);
    qkv_gemm_kernel<<<gq, 256, GEMM_SMEM>>>(rope, bq, bk, bv, qn, kn);

    dim3 ga(13, 16, 4);
    attn_kernel<<<ga, 256, ATT_SMEM>>>();

    ungroup_kernel<<<(NTOK * CDIM / 4 + 255) / 256, 256>>>();

    dim3 go(49, 16);
    out_gemm_kernel<<<go, 256, GEMM_SMEM>>>(bo, out);
}

// round 9
// speedup vs baseline: 2.0310x; 1.1743x over previous
#include <cuda_runtime.h>
#include <cuda_bf16.h>
#include <mma.h>
#include <cstdint>

using namespace nvcuda;
typedef __nv_bfloat16 bf16;

#define NHEADS 16
#define HD     128
#define CDIM   2048
#define NV     6144
#define LT     128
#define NTOK   6272
#define NG     4
#define LVG    1536
#define LSEQ   1664
#define EPSV   1e-6f
#define QSCALE 0.08838834764831845f

// ---------------------------------------------------------------------------
// Scratch
// ---------------------------------------------------------------------------
#define QKV_ELEMS ((size_t)NG * NHEADS * LSEQ * HD)
__device__ bf16 g_Qh[QKV_ELEMS], g_Ql[QKV_ELEMS];
__device__ bf16 g_Kh[QKV_ELEMS], g_Kl[QKV_ELEMS];
__device__ bf16 g_Vh[QKV_ELEMS], g_Vl[QKV_ELEMS];
__device__ float g_OG[(size_t)NG * LSEQ * CDIM];
__device__ bf16 g_XAh[(size_t)NTOK * CDIM], g_XAl[(size_t)NTOK * CDIM];
__device__ bf16 g_XOh[(size_t)NTOK * CDIM], g_XOl[(size_t)NTOK * CDIM];
__device__ bf16 g_Wqh[(size_t)CDIM * CDIM], g_Wql[(size_t)CDIM * CDIM];
__device__ bf16 g_Wkh[(size_t)CDIM * CDIM], g_Wkl[(size_t)CDIM * CDIM];
__device__ bf16 g_Wvh[(size_t)CDIM * CDIM], g_Wvl[(size_t)CDIM * CDIM];
__device__ bf16 g_Woh[(size_t)CDIM * CDIM], g_Wol[(size_t)CDIM * CDIM];

__device__ __forceinline__ void split2(float x, bf16& h, bf16& l) {
    h = __float2bfloat16(x);
    l = __float2bfloat16(x - __bfloat162float(h));
}
__device__ __forceinline__ uint32_t pack2(bf16 a, bf16 b) {
    __nv_bfloat162 t; t.x = a; t.y = b;
    return *reinterpret_cast<uint32_t*>(&t);
}
__device__ __forceinline__ uint32_t smem_u32(const void* p) {
    return (uint32_t)__cvta_generic_to_shared(p);
}
__device__ __forceinline__ void cp16(uint32_t dst, const void* src) {
    asm volatile("cp.async.cg.shared.global [%0], [%1], 16;" :: "r"(dst), "l"(src));
}
__device__ __forceinline__ void cp_commit() {
    asm volatile("cp.async.commit_group;");
}
__device__ __forceinline__ void cp_wait1() {
    asm volatile("cp.async.wait_group 1;");
}
__device__ __forceinline__ void ldsm4(uint32_t* r, uint32_t addr) {
    asm volatile("ldmatrix.sync.aligned.m8n8.x4.shared.b16 {%0,%1,%2,%3},[%4];"
                 : "=r"(r[0]), "=r"(r[1]), "=r"(r[2]), "=r"(r[3]) : "r"(addr));
}
__device__ __forceinline__ void ldsm4t(uint32_t* r, uint32_t addr) {
    asm volatile("ldmatrix.sync.aligned.m8n8.x4.trans.shared.b16 {%0,%1,%2,%3},[%4];"
                 : "=r"(r[0]), "=r"(r[1]), "=r"(r[2]), "=r"(r[3]) : "r"(addr));
}
__device__ __forceinline__ void mma_bf16(float* c, const uint32_t* a,
                                         uint32_t b0, uint32_t b1) {
    asm volatile(
        "mma.sync.aligned.m16n8k16.row.col.f32.bf16.bf16.f32 "
        "{%0,%1,%2,%3},{%4,%5,%6,%7},{%8,%9},{%0,%1,%2,%3};"
        : "+f"(c[0]), "+f"(c[1]), "+f"(c[2]), "+f"(c[3])
        : "r"(a[0]), "r"(a[1]), "r"(a[2]), "r"(a[3]), "r"(b0), "r"(b1));
}

typedef wmma::fragment<wmma::matrix_a, 16, 16, 16, bf16, wmma::row_major>  FragA;
typedef wmma::fragment<wmma::matrix_b, 16, 16, 16, bf16, wmma::col_major>  FragBc;
typedef wmma::fragment<wmma::accumulator, 16, 16, 16, float>               FragC;

// GEMM smem: stage = {Ah,Al,Bh,Bl} each 128x40 bf16; 2 stages = 81,920 B
#define STR   40
#define ARR   (128 * STR)
#define STAGE (4 * ARR)
#define GEMM_SMEM (2 * STAGE * 2)

// ---------------------------------------------------------------------------
// split: fp32 -> bf16 hi/lo
// ---------------------------------------------------------------------------
__global__ __launch_bounds__(256) void split_kernel(
    const float* __restrict__ src, bf16* __restrict__ dh, bf16* __restrict__ dl,
    int n4)
{
    int i = blockIdx.x * 256 + threadIdx.x;
    if (i >= n4) return;
    float4 v = ((const float4*)src)[i];
    union { uint2 u; bf16 b[4]; } h, l;
    split2(v.x, h.b[0], l.b[0]); split2(v.y, h.b[1], l.b[1]);
    split2(v.z, h.b[2], l.b[2]); split2(v.w, h.b[3], l.b[3]);
    ((uint2*)dh)[i] = h.u;
    ((uint2*)dl)[i] = l.u;
}

// ---------------------------------------------------------------------------
// Core pipelined bf16x3 GEMM tile loop (2-stage cp.async double buffer).
// ---------------------------------------------------------------------------
__device__ __forceinline__ void gemm_tile(
    const bf16* __restrict__ Ah, const bf16* __restrict__ Al, size_t a_row0,
    const bf16* __restrict__ Bh, const bf16* __restrict__ Bl, size_t b_row0,
    bf16* smbase, int tid, int wm, int wn, FragC acc[2][4])
{
    const int r  = tid >> 2;                 // 0..63
    const int c8 = (tid & 3) << 3;           // 0,8,16,24
    const size_t aoff  = (a_row0 + r) * CDIM + c8;
    const size_t aoff2 = aoff + (size_t)64 * CDIM;
    const size_t boff  = (b_row0 + r) * CDIM + c8;
    const size_t boff2 = boff + (size_t)64 * CDIM;
    const uint32_t sbase = smem_u32(smbase);
    const uint32_t so  = sbase + (r * STR + c8) * 2;
    const uint32_t so2 = so + 64 * STR * 2;

    cp16(so,                Ah + aoff);
    cp16(so2,               Ah + aoff2);
    cp16(so  + ARR * 2,     Al + aoff);
    cp16(so2 + ARR * 2,     Al + aoff2);
    cp16(so  + 2 * ARR * 2, Bh + boff);
    cp16(so2 + 2 * ARR * 2, Bh + boff2);
    cp16(so  + 3 * ARR * 2, Bl + boff);
    cp16(so2 + 3 * ARR * 2, Bl + boff2);
    cp_commit();

    const int NIT = CDIM / 32;
    for (int it = 0; it < NIT; it++) {
        if (it + 1 < NIT) {
            uint32_t sn  = so  + ((it + 1) & 1) * STAGE * 2;
            uint32_t sn2 = so2 + ((it + 1) & 1) * STAGE * 2;
            int kt = (it + 1) * 32;
            cp16(sn,                Ah + aoff  + kt);
            cp16(sn2,               Ah + aoff2 + kt);
            cp16(sn  + ARR * 2,     Al + aoff  + kt);
            cp16(sn2 + ARR * 2,     Al + aoff2 + kt);
            cp16(sn  + 2 * ARR * 2, Bh + boff  + kt);
            cp16(sn2 + 2 * ARR * 2, Bh + boff2 + kt);
            cp16(sn  + 3 * ARR * 2, Bl + boff  + kt);
            cp16(sn2 + 3 * ARR * 2, Bl + boff2 + kt);
        }
        cp_commit();
        cp_wait1();
        __syncthreads();

        bf16* st  = smbase + (it & 1) * STAGE;
        bf16* sAh = st;
        bf16* sAl = st + ARR;
        bf16* sBh = st + 2 * ARR;
        bf16* sBl = st + 3 * ARR;
        #pragma unroll
        for (int ks = 0; ks < 2; ks++) {
            FragA ah[2], al[2];
            #pragma unroll
            for (int mi = 0; mi < 2; mi++) {
                wmma::load_matrix_sync(ah[mi], sAh + (wm * 32 + mi * 16) * STR + ks * 16, STR);
                wmma::load_matrix_sync(al[mi], sAl + (wm * 32 + mi * 16) * STR + ks * 16, STR);
            }
            #pragma unroll
            for (int f = 0; f < 4; f++) {
                FragBc bh, bl;
                wmma::load_matrix_sync(bh, sBh + (wn * 64 + f * 16) * STR + ks * 16, STR);
                wmma::load_matrix_sync(bl, sBl + (wn * 64 + f * 16) * STR + ks * 16, STR);
                #pragma unroll
                for (int mi = 0; mi < 2; mi++) {
                    wmma::mma_sync(acc[mi][f], ah[mi], bh, acc[mi][f]);
                    wmma::mma_sync(acc[mi][f], ah[mi], bl, acc[mi][f]);
                    wmma::mma_sync(acc[mi][f], al[mi], bh, acc[mi][f]);
                }
            }
        }
        __syncthreads();
    }
}

// ---------------------------------------------------------------------------
// QKV GEMM + fused epilogue.  grid = (49, 16, 3).  2 CTAs/SM target.
// ---------------------------------------------------------------------------
__global__ __launch_bounds__(256, 2) void qkv_gemm_kernel(
    const float* __restrict__ rope,
    const float* __restrict__ bq, const float* __restrict__ bk,
    const float* __restrict__ bv,
    const float* __restrict__ qn, const float* __restrict__ kn)
{
    extern __shared__ char smraw[];
    bf16* smbase = (bf16*)smraw;

    const int tid  = threadIdx.x;
    const int w    = tid >> 5;
    const int wm   = w >> 1;
    const int wn   = w & 1;
    const int mode = blockIdx.z;
    const int head = blockIdx.y;
    const int m0   = blockIdx.x * 128;

    const bf16* Wh = (mode == 0) ? g_Wqh : (mode == 1) ? g_Wkh : g_Wvh;
    const bf16* Wl = (mode == 0) ? g_Wql : (mode == 1) ? g_Wkl : g_Wvl;

    FragC acc[2][4];
    #pragma unroll
    for (int mi = 0; mi < 2; mi++)
        #pragma unroll
        for (int f = 0; f < 4; f++) wmma::fill_fragment(acc[mi][f], 0.0f);

    gemm_tile(g_XAh, g_XAl, (size_t)m0, Wh, Wl, (size_t)head * HD,
              smbase, tid, wm, wn, acc);

    float* sC = (float*)smraw;              // 128 x 128 = 64 KB
    #pragma unroll
    for (int mi = 0; mi < 2; mi++)
        #pragma unroll
        for (int f = 0; f < 4; f++)
            wmma::store_matrix_sync(sC + (wm * 32 + mi * 16) * 128 + wn * 64 + f * 16,
                                    acc[mi][f], 128, wmma::mem_row_major);
    __syncthreads();

    const float* bias = (mode == 0) ? bq : (mode == 1) ? bk : bv;
    const int r   = tid >> 1;
    const int c0  = (tid & 1) * 64;
    const int tok = m0 + r;

    float vals[64];
    #pragma unroll
    for (int c = 0; c < 64; c++)
        vals[c] = sC[r * 128 + c0 + c] + bias[head * HD + c0 + c];

    if (mode < 2) {
        const float* wgt = (mode == 0) ? qn : kn;
        float ss = 0.f;
        #pragma unroll
        for (int c = 0; c < 64; c++) ss += vals[c] * vals[c];
        ss += __shfl_xor_sync(0xffffffffu, ss, 1);
        float rstd = rsqrtf(ss * (1.0f / HD) + EPSV);
        #pragma unroll
        for (int c = 0; c < 64; c++) vals[c] = vals[c] * rstd * wgt[c0 + c];

        if (tok < NV) {
            const float* rp = rope + (size_t)tok * 256 + c0 * 2;
            #pragma unroll
            for (int i = 0; i < 32; i++) {
                float4 r4 = *(const float4*)(rp + i * 4);
                float x0 = vals[2 * i], x1 = vals[2 * i + 1];
                vals[2 * i]     = r4.x * x0 + r4.y * x1;
                vals[2 * i + 1] = r4.z * x0 + r4.w * x1;
            }
        }
        if (mode == 0) {
            #pragma unroll
            for (int c = 0; c < 64; c++) vals[c] *= QSCALE;
        }
    }

    bf16* dsth = (mode == 0) ? g_Qh : (mode == 1) ? g_Kh : g_Vh;
    bf16* dstl = (mode == 0) ? g_Ql : (mode == 1) ? g_Kl : g_Vl;

    union { uint4 v; bf16 b[8]; } ph, pl;
    if (tok < NV) {
        int t = tok / 768, rem = tok - t * 768;
        int hh = rem >> 5, ww = rem & 31;
        int g   = (hh / 12) * 2 + (ww >> 4);
        int pos = t * 192 + (hh % 12) * 16 + (ww & 15);
        size_t off = ((size_t)((g * NHEADS + head) * LSEQ + pos)) * HD + c0;
        #pragma unroll
        for (int u = 0; u < 8; u++) {
            #pragma unroll
            for (int j = 0; j < 8; j++) split2(vals[u * 8 + j], ph.b[j], pl.b[j]);
            *(uint4*)(dsth + off + u * 8) = ph.v;
            *(uint4*)(dstl + off + u * 8) = pl.v;
        }
    } else {
        int pos = LVG + (tok - NV);
        #pragma unroll
        for (int u = 0; u < 8; u++) {
            #pragma unroll
            for (int j = 0; j < 8; j++) split2(vals[u * 8 + j], ph.b[j], pl.b[j]);
            #pragma unroll
            for (int g = 0; g < NG; g++) {
                size_t off = ((size_t)((g * NHEADS + head) * LSEQ + pos)) * HD + c0;
                *(uint4*)(dsth + off + u * 8) = ph.v;
                *(uint4*)(dstl + off + u * 8) = pl.v;
            }
        }
    }
}

// ---------------------------------------------------------------------------
// Attention: single-pass online softmax, raw mma.sync, bf16x3,
// 2-stage cp.async pipelined K/V.  grid = (13, 16, 4)
// ---------------------------------------------------------------------------
#define KSTR 136
#define KVA  (64 * KSTR * 2)                          // bytes per KV array
#define ATT_SMEM ((2 * 128 * KSTR + 2 * 4 * 64 * KSTR) * 2)   // 208,896 B

__global__ __launch_bounds__(256, 1) void attn_kernel()
{
    extern __shared__ char smraw[];
    bf16* sQh = (bf16*)smraw;
    bf16* sQl = sQh + 128 * KSTR;

    const int tid  = threadIdx.x;
    const int lane = tid & 31;
    const int w    = tid >> 5;
    const int q0   = blockIdx.x * 128;
    const int h    = blockIdx.y;
    const int g    = blockIdx.z;
    const size_t base = (size_t)(g * NHEADS + h) * LSEQ * HD;
    const bf16 *Qh = g_Qh + base, *Ql = g_Ql + base;
    const bf16 *Kh = g_Kh + base, *Kl = g_Kl + base;
    const bf16 *Vh = g_Vh + base, *Vl = g_Vl + base;

    const uint32_t kvbase = smem_u32(smraw) + 2 * 128 * KSTR * 2;

    #define KV_LOAD(s, kt) do {                                           \
        uint32_t _b = kvbase + (uint32_t)(s) * (4 * KVA);                 \
        _Pragma("unroll")                                                 \
        for (int _i = 0; _i < 4; _i++) {                                  \
            int _idx = tid + _i * 256;                                    \
            int _r = _idx >> 4, _cu = (_idx & 15) << 3;                   \
            size_t _go = (size_t)((kt) + _r) * HD + _cu;                  \
            uint32_t _so = (uint32_t)(_r * KSTR + _cu) * 2;               \
            cp16(_b + _so,           Kh + _go);                           \
            cp16(_b + KVA + _so,     Kl + _go);                           \
            cp16(_b + 2 * KVA + _so, Vh + _go);                           \
            cp16(_b + 3 * KVA + _so, Vl + _go);                           \
        }                                                                 \
    } while (0)

    // prologue: stage 0 async, then Q tile (plain loads)
    KV_LOAD(0, 0);
    cp_commit();

    #pragma unroll
    for (int i = 0; i < 8; i++) {
        int idx = tid + i * 256;
        int r = idx >> 4, cu = (idx & 15) << 3;
        size_t go = (size_t)(q0 + r) * HD + cu;
        *(uint4*)(sQh + r * KSTR + cu) = *(const uint4*)(Qh + go);
        *(uint4*)(sQl + r * KSTR + cu) = *(const uint4*)(Ql + go);
    }

    float m0 = -1e30f, m1 = -1e30f, l0 = 0.f, l1 = 0.f;
    float o[16][4];
    #pragma unroll
    for (int d = 0; d < 16; d++)
        #pragma unroll
        for (int j = 0; j < 4; j++) o[d][j] = 0.f;

    const int grp = lane >> 3, l7 = lane & 7;
    const int a_row  = w * 16 + ((grp & 1) << 3) + l7;
    const int a_col8 = (grp >> 1) << 3;
    const uint32_t qoffh = smem_u32(sQh) + (a_row * KSTR + a_col8) * 2;
    const uint32_t qoffl = smem_u32(sQl) + (a_row * KSTR + a_col8) * 2;
    const int b_rowoff = ((grp >> 1) << 3) + l7;
    const int b_col8   = (grp & 1) << 3;
    const int v_rowoff = ((grp & 1) << 3) + l7;
    const int v_col8   = (grp >> 1) << 3;

    __syncthreads();

    const int NKT = LSEQ / 64;   // 26
    for (int it = 0; it < NKT; it++) {
        if (it + 1 < NKT) KV_LOAD((it + 1) & 1, (it + 1) * 64);
        cp_commit();
        cp_wait1();
        __syncthreads();

        const uint32_t kb  = kvbase + (uint32_t)(it & 1) * (4 * KVA);
        const uint32_t kbh = kb, kbl = kb + KVA;
        const uint32_t vbh = kb + 2 * KVA, vbl = kb + 3 * KVA;

        float sacc[8][4];
        #pragma unroll
        for (int n = 0; n < 8; n++)
            #pragma unroll
            for (int j = 0; j < 4; j++) sacc[n][j] = 0.f;

        #pragma unroll
        for (int kc = 0; kc < 8; kc++) {
            uint32_t qh[4], ql[4];
            ldsm4(qh, qoffh + kc * 32);
            ldsm4(ql, qoffl + kc * 32);
            #pragma unroll
            for (int np = 0; np < 4; np++) {
                uint32_t koff = ((np * 16 + b_rowoff) * KSTR + kc * 16 + b_col8) * 2;
                uint32_t kh4[4], kl4[4];
                ldsm4(kh4, kbh + koff);
                ldsm4(kl4, kbl + koff);
                mma_bf16(sacc[2*np],   qh, kh4[0], kh4[1]);
                mma_bf16(sacc[2*np],   qh, kl4[0], kl4[1]);
                mma_bf16(sacc[2*np],   ql, kh4[0], kh4[1]);
                mma_bf16(sacc[2*np+1], qh, kh4[2], kh4[3]);
                mma_bf16(sacc[2*np+1], qh, kl4[2], kl4[3]);
                mma_bf16(sacc[2*np+1], ql, kh4[2], kh4[3]);
            }
        }

        float mt0 = -1e30f, mt1 = -1e30f;
        #pragma unroll
        for (int n = 0; n < 8; n++) {
            mt0 = fmaxf(mt0, fmaxf(sacc[n][0], sacc[n][1]));
            mt1 = fmaxf(mt1, fmaxf(sacc[n][2], sacc[n][3]));
        }
        mt0 = fmaxf(mt0, __shfl_xor_sync(0xffffffffu, mt0, 1));
        mt0 = fmaxf(mt0, __shfl_xor_sync(0xffffffffu, mt0, 2));
        mt1 = fmaxf(mt1, __shfl_xor_sync(0xffffffffu, mt1, 1));
        mt1 = fmaxf(mt1, __shfl_xor_sync(0xffffffffu, mt1, 2));
        float mn0 = fmaxf(m0, mt0), mn1 = fmaxf(m1, mt1);
        float al0 = __expf(m0 - mn0), al1 = __expf(m1 - mn1);
        m0 = mn0; m1 = mn1;

        float ls0 = 0.f, ls1 = 0.f;
        uint32_t pah[8][2], pal[8][2];
        #pragma unroll
        for (int n = 0; n < 8; n++) {
            float p0 = __expf(sacc[n][0] - mn0), p1 = __expf(sacc[n][1] - mn0);
            float p2 = __expf(sacc[n][2] - mn1), p3 = __expf(sacc[n][3] - mn1);
            ls0 += p0 + p1; ls1 += p2 + p3;
            bf16 h0, e0, h1, e1, h2, e2, h3, e3;
            split2(p0, h0, e0); split2(p1, h1, e1);
            split2(p2, h2, e2); split2(p3, h3, e3);
            pah[n][0] = pack2(h0, h1); pal[n][0] = pack2(e0, e1);
            pah[n][1] = pack2(h2, h3); pal[n][1] = pack2(e2, e3);
        }
        l0 = l0 * al0 + ls0;
        l1 = l1 * al1 + ls1;
        #pragma unroll
        for (int d = 0; d < 16; d++) {
            o[d][0] *= al0; o[d][1] *= al0;
            o[d][2] *= al1; o[d][3] *= al1;
        }

        #pragma unroll
        for (int kc = 0; kc < 4; kc++) {
            uint32_t ah[4]  = { pah[2*kc][0], pah[2*kc][1], pah[2*kc+1][0], pah[2*kc+1][1] };
            uint32_t alo[4] = { pal[2*kc][0], pal[2*kc][1], pal[2*kc+1][0], pal[2*kc+1][1] };
            #pragma unroll
            for (int dp = 0; dp < 8; dp++) {
                uint32_t voff = ((kc * 16 + v_rowoff) * KSTR + dp * 16 + v_col8) * 2;
                uint32_t vh4[4], vl4[4];
                ldsm4t(vh4, vbh + voff);
                ldsm4t(vl4, vbl + voff);
                mma_bf16(o[2*dp],   ah,  vh4[0], vh4[1]);
                mma_bf16(o[2*dp],   ah,  vl4[0], vl4[1]);
                mma_bf16(o[2*dp],   alo, vh4[0], vh4[1]);
                mma_bf16(o[2*dp+1], ah,  vh4[2], vh4[3]);
                mma_bf16(o[2*dp+1], ah,  vl4[2], vl4[3]);
                mma_bf16(o[2*dp+1], alo, vh4[2], vh4[3]);
            }
        }
        __syncthreads();
    }
    #undef KV_LOAD

    l0 += __shfl_xor_sync(0xffffffffu, l0, 1);
    l0 += __shfl_xor_sync(0xffffffffu, l0, 2);
    l1 += __shfl_xor_sync(0xffffffffu, l1, 1);
    l1 += __shfl_xor_sync(0xffffffffu, l1, 2);
    float inv0 = 1.f / l0, inv1 = 1.f / l1;

    int r0 = q0 + w * 16 + (lane >> 2);
    int r1 = r0 + 8;
    int cb = h * HD + (lane & 3) * 2;
    float* O0 = g_OG + (size_t)(g * LSEQ + r0) * CDIM + cb;
    float* O1 = g_OG + (size_t)(g * LSEQ + r1) * CDIM + cb;
    #pragma unroll
    for (int d = 0; d < 16; d++) {
        float2 v0 = { o[d][0] * inv0, o[d][1] * inv0 };
        float2 v1 = { o[d][2] * inv1, o[d][3] * inv1 };
        *(float2*)(O0 + d * 8) = v0;
        *(float2*)(O1 + d * 8) = v1;
    }
}

// ---------------------------------------------------------------------------
// Ungroup (writes bf16 hi/lo directly)
// ---------------------------------------------------------------------------
__global__ __launch_bounds__(256) void ungroup_kernel()
{
    int i = blockIdx.x * 256 + threadIdx.x;
    if (i >= NTOK * CDIM / 4) return;
    int tok = i >> 9;
    int c4  = (i & 511) << 2;
    float4 res;
    if (tok < NV) {
        int t = tok / 768, rem = tok - t * 768;
        int hh = rem >> 5, ww = rem & 31;
        int g   = (hh / 12) * 2 + (ww >> 4);
        int pos = t * 192 + (hh % 12) * 16 + (ww & 15);
        res = *(const float4*)(g_OG + ((size_t)(g * LSEQ + pos)) * CDIM + c4);
    } else {
        int pos = LVG + tok - NV;
        float4 a = *(const float4*)(g_OG + ((size_t)(0 * LSEQ + pos)) * CDIM + c4);
        float4 b = *(const float4*)(g_OG + ((size_t)(1 * LSEQ + pos)) * CDIM + c4);
        float4 c = *(const float4*)(g_OG + ((size_t)(2 * LSEQ + pos)) * CDIM + c4);
        float4 d = *(const float4*)(g_OG + ((size_t)(3 * LSEQ + pos)) * CDIM + c4);
        res.x = (a.x + b.x + c.x + d.x) * 0.25f;
        res.y = (a.y + b.y + c.y + d.y) * 0.25f;
        res.z = (a.z + b.z + c.z + d.z) * 0.25f;
        res.w = (a.w + b.w + c.w + d.w) * 0.25f;
    }
    union { uint2 u; bf16 b[4]; } h, l;
    split2(res.x, h.b[0], l.b[0]); split2(res.y, h.b[1], l.b[1]);
    split2(res.z, h.b[2], l.b[2]); split2(res.w, h.b[3], l.b[3]);
    ((uint2*)g_XOh)[i] = h.u;
    ((uint2*)g_XOl)[i] = l.u;
}

// ---------------------------------------------------------------------------
// Output GEMM.  grid = (49, 16).  2 CTAs/SM target.
// ---------------------------------------------------------------------------
__global__ __launch_bounds__(256, 2) void out_gemm_kernel(
    const float* __restrict__ bo, float* __restrict__ out)
{
    extern __shared__ char smraw[];
    bf16* smbase = (bf16*)smraw;

    const int tid  = threadIdx.x;
    const int w    = tid >> 5;
    const int wm   = w >> 1;
    const int wn   = w & 1;
    const int head = blockIdx.y;
    const int m0   = blockIdx.x * 128;

    FragC acc[2][4];
    #pragma unroll
    for (int mi = 0; mi < 2; mi++)
        #pragma unroll
        for (int f = 0; f < 4; f++) wmma::fill_fragment(acc[mi][f], 0.0f);

    gemm_tile(g_XOh, g_XOl, (size_t)m0, g_Woh, g_Wol, (size_t)head * HD,
              smbase, tid, wm, wn, acc);

    float* sC = (float*)smraw;
    #pragma unroll
    for (int mi = 0; mi < 2; mi++)
        #pragma unroll
        for (int f = 0; f < 4; f++)
            wmma::store_matrix_sync(sC + (wm * 32 + mi * 16) * 128 + wn * 64 + f * 16,
                                    acc[mi][f], 128, wmma::mem_row_major);
    __syncthreads();

    const int r  = tid >> 1;
    const int c0 = (tid & 1) * 64;
    const int tok = m0 + r;
    float* d = out + (size_t)tok * CDIM + head * HD + c0;
    #pragma unroll
    for (int u = 0; u < 16; u++) {
        float4 v;
        v.x = sC[r * 128 + c0 + u*4 + 0] + bo[head * HD + c0 + u*4 + 0];
        v.y = sC[r * 128 + c0 + u*4 + 1] + bo[head * HD + c0 + u*4 + 1];
        v.z = sC[r * 128 + c0 + u*4 + 2] + bo[head * HD + c0 + u*4 + 2];
        v.w = sC[r * 128 + c0 + u*4 + 3] + bo[head * HD + c0 + u*4 + 3];
        *(float4*)(d + u * 4) = v;
    }
}

// ---------------------------------------------------------------------------
extern "C" void kernel_launch(void* const* d_in, const int* in_sizes, int n_in,
                              void* d_out, int out_size)
{
    const float* vis  = (const float*)d_in[0];
    const float* txt  = (const float*)d_in[1];
    const float* rope = (const float*)d_in[2];
    const float* Wq   = (const float*)d_in[3];
    const float* bq   = (const float*)d_in[4];
    const float* Wk   = (const float*)d_in[5];
    const float* bk   = (const float*)d_in[6];
    const float* Wv   = (const float*)d_in[7];
    const float* bv   = (const float*)d_in[8];
    const float* qn   = (const float*)d_in[9];
    const float* kn   = (const float*)d_in[10];
    const float* Wo   = (const float*)d_in[11];
    const float* bo   = (const float*)d_in[12];
    float* out = (float*)d_out;
    (void)in_sizes; (void)n_in; (void)out_size;

    cudaFuncSetAttribute(qkv_gemm_kernel, cudaFuncAttributeMaxDynamicSharedMemorySize, GEMM_SMEM);
    cudaFuncSetAttribute(out_gemm_kernel, cudaFuncAttributeMaxDynamicSharedMemorySize, GEMM_SMEM);
    cudaFuncSetAttribute(attn_kernel,     cudaFuncAttributeMaxDynamicSharedMemorySize, ATT_SMEM);

    bf16* xh; bf16* xl;
    cudaGetSymbolAddress((void**)&xh, g_XAh);
    cudaGetSymbolAddress((void**)&xl, g_XAl);
    split_kernel<<<(NV * CDIM / 4 + 255) / 256, 256>>>(vis, xh, xl, NV * CDIM / 4);
    split_kernel<<<(LT * CDIM / 4 + 255) / 256, 256>>>(
        txt, xh + (size_t)NV * CDIM, xl + (size_t)NV * CDIM, LT * CDIM / 4);

    bf16 *wh, *wl;
    cudaGetSymbolAddress((void**)&wh, g_Wqh); cudaGetSymbolAddress((void**)&wl, g_Wql);
    split_kernel<<<(CDIM * CDIM / 4 + 255) / 256, 256>>>(Wq, wh, wl, CDIM * CDIM / 4);
    cudaGetSymbolAddress((void**)&wh, g_Wkh); cudaGetSymbolAddress((void**)&wl, g_Wkl);
    split_kernel<<<(CDIM * CDIM / 4 + 255) / 256, 256>>>(Wk, wh, wl, CDIM * CDIM / 4);
    cudaGetSymbolAddress((void**)&wh, g_Wvh); cudaGetSymbolAddress((void**)&wl, g_Wvl);
    split_kernel<<<(CDIM * CDIM / 4 + 255) / 256, 256>>>(Wv, wh, wl, CDIM * CDIM / 4);
    cudaGetSymbolAddress((void**)&wh, g_Woh); cudaGetSymbolAddress((void**)&wl, g_Wol);
    split_kernel<<<(CDIM * CDIM / 4 + 255) / 256, 256>>>(Wo, wh, wl, CDIM * CDIM / 4);

    dim3 gq(49, 16, 3);
    qkv_gemm_kernel<<<gq, 256, GEMM_SMEM>>>(rope, bq, bk, bv, qn, kn);

    dim3 ga(13, 16, 4);
    attn_kernel<<<ga, 256, ATT_SMEM>>>();

    ungroup_kernel<<<(NTOK * CDIM / 4 + 255) / 256, 256>>>();

    dim3 go(49, 16);
    out_gemm_kernel<<<go, 256, GEMM_SMEM>>>(bo, out);
}